// round 9
// baseline (speedup 1.0000x reference)
#include <cuda_runtime.h>
#include <cuda_fp16.h>
#include <math.h>
#include <stdint.h>

typedef __half fp16;

#define BATCH 8192
#define PDIM  512
#define H1DIM 1024
#define H2DIM 512
#define NOUTD 1024
#define MMDIM 512
#define NCODE 2048
#define KSTEPS 16

// ---------------- device scratch (no allocations allowed) -------------------
__device__ float g_v [(size_t)BATCH * NCODE];   // FISTA v (fp32 state)
__device__ float g_a0[(size_t)BATCH * NCODE];   // alpha (fp32 state)

// activations: single fp16 (GEMM inputs)
__device__ fp16 g_xs[(size_t)BATCH*PDIM];
__device__ fp16 g_h1[(size_t)BATCH*H1DIM];
__device__ fp16 g_h2[(size_t)BATCH*H2DIM];
__device__ fp16 g_yb[(size_t)BATCH*NOUTD];
__device__ fp16 g_zh[(size_t)BATCH*MMDIM];   // z in fp16 (RSUB aux)
__device__ fp16 g_vs[(size_t)BATCH*NCODE];   // v fp16 shadow (r-GEMM input)
__device__ fp16 g_rs[(size_t)BATCH*MMDIM];   // r
__device__ fp16 g_ap[(size_t)BATCH*NCODE];   // final alpha fp16 (yhat GEMM input)

// weights / operators: single fp16 (rounded once)
__device__ fp16 g_w1[(size_t)H1DIM*PDIM];    // W1^T
__device__ fp16 g_w2[(size_t)H2DIM*H1DIM];   // W2^T
__device__ fp16 g_w3[(size_t)NOUTD*H2DIM];   // W3^T
__device__ fp16 g_m [(size_t)MMDIM*NOUTD];   // M  (as stored)
__device__ fp16 g_aa[(size_t)MMDIM*NCODE];   // A  (as stored)
__device__ fp16 g_at[(size_t)NCODE*MMDIM];   // A^T
__device__ fp16 g_ps[(size_t)NOUTD*NCODE];   // Psi (as stored)

// ---------------- PTX helpers (legal on base compute_103 target) ------------
__device__ __forceinline__ uint32_t smem_u32(const void* p) {
    uint32_t a;
    asm("{ .reg .u64 t; cvta.to.shared.u64 t, %1; cvt.u32.u64 %0, t; }" : "=r"(a) : "l"(p));
    return a;
}
__device__ __forceinline__ void cp16(uint32_t d, const void* s) {
    asm volatile("cp.async.cg.shared.global [%0], [%1], 16;" :: "r"(d), "l"(s) : "memory");
}
#define CP_COMMIT() asm volatile("cp.async.commit_group;" ::: "memory")
#define CP_WAIT0()  asm volatile("cp.async.wait_group 0;" ::: "memory")
#define CP_WAIT1()  asm volatile("cp.async.wait_group 1;" ::: "memory")

#define LDSM4(r0, r1, r2, r3, a) \
    asm volatile("ldmatrix.sync.aligned.m8n8.x4.shared.b16 {%0,%1,%2,%3}, [%4];" \
                 : "=r"(r0), "=r"(r1), "=r"(r2), "=r"(r3) : "r"(a))

#define MMA16816(c, a, b) \
    asm volatile("mma.sync.aligned.m16n8k16.row.col.f32.f16.f16.f32 " \
                 "{%0,%1,%2,%3}, {%4,%5,%6,%7}, {%8,%9}, {%0,%1,%2,%3};" \
                 : "+f"((c)[0]), "+f"((c)[1]), "+f"((c)[2]), "+f"((c)[3]) \
                 : "r"((a)[0]), "r"((a)[1]), "r"((a)[2]), "r"((a)[3]), \
                   "r"((b)[0]), "r"((b)[1]))

// ---------------- GEMM constants ---------------------------------------------
#define ROW_B   144
#define TILE_B  (128 * ROW_B)            // 18432 B per operand tile
#define STAGE_B (2 * TILE_B)             // A, B = 36864 B
#define SMEM_BYTES (3 * STAGE_B)         // 3 stages = 110592 B

enum { EPI_GELU = 0, EPI_YBG, EPI_ZSUB, EPI_RSUB, EPI_FISTA, EPI_ADD };

__device__ __forceinline__ float gelu_exact(float x) {
    return 0.5f * x * (1.0f + erff(x * 0.70710678118654752440f));
}
__device__ __forceinline__ void store2h(fp16* H, size_t idx, float o0, float o1) {
    *(__half2*)(H + idx) = __halves2half2(__float2half_rn(o0), __float2half_rn(o1));
}

// ---------------------------------------------------------------------------
// Warp-MMA GEMM: D[128x128 tile] = A[M,K] * (B[N,K])^T, fp32 acc, single fp16
// product, 3-stage cp.async pipeline, fused epilogue.
// ---------------------------------------------------------------------------
template <int EPI>
__global__ void __launch_bounds__(256, 1)
wgemm(const fp16* __restrict__ Ag, const fp16* __restrict__ Bg,
      int Ndim, int Kdim,
      float* __restrict__ C0, fp16* __restrict__ Ch,
      const float* __restrict__ auxF,      // bias / bvec / y_bg
      const fp16* __restrict__ auxH,       // zh for RSUB
      float* __restrict__ vbuf,            // FISTA v   (fp32 state, in/out)
      float* __restrict__ abuf,            // FISTA alpha (fp32 state, in/out)
      fp16* __restrict__ vho,              // v fp16 shadow out
      const float* __restrict__ leta, const float* __restrict__ ltau,
      int kidx, float beta)
{
    extern __shared__ char dyn[];
    const uint32_t sbase = smem_u32(dyn);

    const int tid = threadIdx.x;
    const int wid = tid >> 5;
    const int lid = tid & 31;
    const int m0  = blockIdx.y * 128;
    const int n0  = blockIdx.x * 128;
    const int m_w = (wid >> 2) * 64;
    const int n_w = (wid & 3) * 32;

    // ---- loader plan: 8 cp.async x 16B per thread per stage ------------------
    const fp16* gp[8];
    uint32_t so[8];
    {
        const fp16* srcs[2] = { Ag, Bg };
#pragma unroll
        for (int it = 0; it < 8; it++) {
            const int op  = it >> 2;                    // 0:A 1:B
            const int row = (it & 3) * 32 + (tid >> 3);
            const int seg = tid & 7;
            const int rb  = (op == 0) ? m0 : n0;
            gp[it] = srcs[op] + (size_t)(rb + row) * Kdim + seg * 8;
            so[it] = (uint32_t)(op * TILE_B + row * ROW_B + seg * 16);
        }
    }

    // ---- ldmatrix per-lane offsets -------------------------------------------
    const int aRow = (lid & 7) + ((lid >> 3) & 1) * 8;
    const int aK   = ((lid >> 4) & 1) * 8;
    const int bRow = (lid & 7) + ((lid >> 4) & 1) * 8;
    const int bK   = ((lid >> 3) & 1) * 8;
    const uint32_t aOff = (uint32_t)((m_w + aRow) * ROW_B + aK * 2);
    const uint32_t bOff = (uint32_t)((n_w + bRow) * ROW_B + bK * 2);

    float acc[4][4][4];
#pragma unroll
    for (int i = 0; i < 4; i++)
#pragma unroll
        for (int j = 0; j < 4; j++)
#pragma unroll
            for (int c = 0; c < 4; c++) acc[i][j][c] = 0.0f;

    const int S = Kdim >> 6;

#pragma unroll
    for (int it = 0; it < 8; it++) cp16(sbase + so[it], gp[it]);
    CP_COMMIT();
    if (S > 1) {
#pragma unroll
        for (int it = 0; it < 8; it++) cp16(sbase + STAGE_B + so[it], gp[it] + 64);
        CP_COMMIT();
    }

    int cb = 0, pb = 2;
    for (int s = 0; s < S; s++) {
        if (s + 2 < S) { CP_WAIT1(); } else { CP_WAIT0(); }
        __syncthreads();
        if (s + 2 < S) {
            const uint32_t db = sbase + (uint32_t)(pb * STAGE_B);
            const int k0 = (s + 2) * 64;
#pragma unroll
            for (int it = 0; it < 8; it++) cp16(db + so[it], gp[it] + k0);
            CP_COMMIT();
        }
        const uint32_t st = sbase + (uint32_t)(cb * STAGE_B);

#pragma unroll
        for (int kk = 0; kk < 4; kk++) {
            uint32_t ah[4][4], bh[4][2];
#pragma unroll
            for (int i = 0; i < 4; i++) {
                LDSM4(ah[i][0], ah[i][1], ah[i][2], ah[i][3],
                      st + aOff + i * (16 * ROW_B) + kk * 32);
            }
#pragma unroll
            for (int j = 0; j < 2; j++) {
                uint32_t r0, r1, r2, r3;
                LDSM4(r0, r1, r2, r3,
                      st + TILE_B + bOff + j * (16 * ROW_B) + kk * 32);
                bh[2 * j][0] = r0; bh[2 * j][1] = r1;
                bh[2 * j + 1][0] = r2; bh[2 * j + 1][1] = r3;
            }
#pragma unroll
            for (int i = 0; i < 4; i++)
#pragma unroll
                for (int j = 0; j < 4; j++)
                    MMA16816(acc[i][j], ah[i], bh[j]);
        }
        cb = (cb == 2) ? 0 : cb + 1;
        pb = (pb == 2) ? 0 : pb + 1;
    }

    // ---- fused epilogue -------------------------------------------------------
    float eta = 0.0f, thr = 0.0f;
    bool k0f = false, last = false;
    if (EPI == EPI_FISTA) {
        eta = expf(leta[kidx]);  eta = fminf(fmaxf(eta, 1e-8f), 10.0f);
        float tau = expf(ltau[kidx]); tau = fminf(fmaxf(tau, 1e-8f), 10.0f);
        thr = eta * tau;
        k0f  = (kidx == 0);
        last = (kidx == KSTEPS - 1);
    }

#pragma unroll
    for (int i = 0; i < 4; i++) {
#pragma unroll
        for (int j = 0; j < 4; j++) {
#pragma unroll
            for (int half = 0; half < 2; half++) {
                const int row = m0 + m_w + i * 16 + (lid >> 2) + half * 8;
                const int col = n0 + n_w + j * 8 + (lid & 3) * 2;
                const size_t idx = (size_t)row * Ndim + col;
                float o0 = acc[i][j][half * 2];
                float o1 = acc[i][j][half * 2 + 1];

                if (EPI == EPI_GELU) {
                    float2 bv = *(const float2*)&auxF[col];
                    o0 = gelu_exact(o0 + bv.x);
                    o1 = gelu_exact(o1 + bv.y);
                    store2h(Ch, idx, o0, o1);
                } else if (EPI == EPI_YBG) {
                    float2 bv = *(const float2*)&auxF[col];
                    o0 += bv.x; o1 += bv.y;
                    *(float2*)&C0[idx] = make_float2(o0, o1);
                    store2h(Ch, idx, o0, o1);
                } else if (EPI == EPI_ZSUB) {               // z = b - acc (+ zh fp16)
                    float2 av = *(const float2*)&auxF[idx];
                    float z0 = av.x - o0, z1 = av.y - o1;
                    *(float2*)&C0[idx] = make_float2(z0, z1);
                    store2h(Ch, idx, z0, z1);
                } else if (EPI == EPI_RSUB) {               // r = acc - z (fp16 aux)
                    __half2 zv = *(const __half2*)&auxH[idx];
                    store2h(Ch, idx, o0 - __half2float(__low2half(zv)),
                                     o1 - __half2float(__high2half(zv)));
                } else if (EPI == EPI_FISTA) {
                    float v0 = 0.f, v1 = 0.f, a0o = 0.f, a1o = 0.f;
                    if (!k0f) {
                        float2 vv = *(const float2*)&vbuf[idx];
                        v0 = vv.x; v1 = vv.y;
                        float2 av = *(const float2*)&abuf[idx];
                        a0o = av.x; a1o = av.y;
                    }
                    float u0 = v0 - eta * o0, u1 = v1 - eta * o1;
                    float a0n = copysignf(fmaxf(fabsf(u0) - thr, 0.0f), u0);
                    float a1n = copysignf(fmaxf(fabsf(u1) - thr, 0.0f), u1);
                    if (!last) {
                        float vn0 = a0n + beta * (a0n - a0o);
                        float vn1 = a1n + beta * (a1n - a1o);
                        *(float2*)&abuf[idx] = make_float2(a0n, a1n);
                        *(float2*)&vbuf[idx] = make_float2(vn0, vn1);
                        store2h(vho, idx, vn0, vn1);
                    } else {
                        *(float2*)&C0[idx] = make_float2(a0n, a1n);   // o_alpha
                        store2h(Ch, idx, a0n, a1n);                    // ap fp16
                    }
                } else {                                    // EPI_ADD: yhat
                    float2 yv = *(const float2*)&auxF[idx];
                    *(float2*)&C0[idx] = make_float2(o0 + yv.x, o1 + yv.y);
                }
            }
        }
    }
}

// ---------------- prep kernels ------------------------------------------------
__global__ void round_kernel(const float4* __restrict__ s, fp16* __restrict__ o, int n4)
{
    int i = blockIdx.x * blockDim.x + threadIdx.x;
    if (i < n4) {
        float4 v = s[i];
        size_t idx = (size_t)i * 4;
        *(__half2*)(o + idx)     = __halves2half2(__float2half_rn(v.x), __float2half_rn(v.y));
        *(__half2*)(o + idx + 2) = __halves2half2(__float2half_rn(v.z), __float2half_rn(v.w));
    }
}

// transpose + round: src [R,C] fp32 -> dst [C,R] fp16
__global__ void tround_kernel(const float* __restrict__ s, fp16* __restrict__ o,
                              int R, int C)
{
    __shared__ float t[32][33];
    const int bx = blockIdx.x * 32;
    const int by = blockIdx.y * 32;
    const int x = threadIdx.x, y = threadIdx.y;
#pragma unroll
    for (int i = 0; i < 4; i++)
        t[y + i * 8][x] = s[(size_t)(by + y + i * 8) * C + bx + x];
    __syncthreads();
#pragma unroll
    for (int i = 0; i < 4; i++)
        o[(size_t)(bx + y + i * 8) * R + by + x] = __float2half_rn(t[x][y + i * 8]);
}

// r0 = -z  (flip sign bits of fp16 pairs)
__global__ void negh_kernel(const uint32_t* __restrict__ s, uint32_t* __restrict__ d, int n2)
{
    int i = blockIdx.x * blockDim.x + threadIdx.x;
    if (i < n2) d[i] = s[i] ^ 0x80008000u;
}

// ---------------------------------------------------------------------------
extern "C" void kernel_launch(void* const* d_in, const int* in_sizes, int n_in,
                              void* d_out, int out_size)
{
    const float* x    = (const float*)d_in[0];
    const float* bvec = (const float*)d_in[1];
    const float* W1   = (const float*)d_in[2];
    const float* b1   = (const float*)d_in[3];
    const float* W2   = (const float*)d_in[4];
    const float* b2   = (const float*)d_in[5];
    const float* W3   = (const float*)d_in[6];
    const float* b3   = (const float*)d_in[7];
    const float* A    = (const float*)d_in[8];
    const float* leta = (const float*)d_in[9];
    const float* ltau = (const float*)d_in[10];
    const float* Psi  = (const float*)d_in[11];
    const float* Mmat = (const float*)d_in[12];

    float* out     = (float*)d_out;
    float* o_ybg   = out;
    float* o_z     = o_ybg   + (size_t)BATCH * NOUTD;
    float* o_alpha = o_z     + (size_t)BATCH * MMDIM;
    float* o_yhat  = o_alpha + (size_t)BATCH * NCODE;

#define SYM(p, s) void* p##_; cudaGetSymbolAddress(&p##_, s); auto* p = (decltype(&s[0]))p##_
    SYM(vbuf, g_v);  SYM(abuf, g_a0);
    SYM(xs, g_xs);   SYM(h1, g_h1);   SYM(h2, g_h2);   SYM(yb, g_yb);
    SYM(zh, g_zh);   SYM(vs, g_vs);   SYM(rs, g_rs);   SYM(ap, g_ap);
    SYM(w1, g_w1);   SYM(w2, g_w2);   SYM(w3, g_w3);
    SYM(mw, g_m);    SYM(aa, g_aa);   SYM(at, g_at);   SYM(ps, g_ps);
#undef SYM

    cudaFuncSetAttribute((void*)wgemm<EPI_GELU>,  cudaFuncAttributeMaxDynamicSharedMemorySize, SMEM_BYTES);
    cudaFuncSetAttribute((void*)wgemm<EPI_YBG>,   cudaFuncAttributeMaxDynamicSharedMemorySize, SMEM_BYTES);
    cudaFuncSetAttribute((void*)wgemm<EPI_ZSUB>,  cudaFuncAttributeMaxDynamicSharedMemorySize, SMEM_BYTES);
    cudaFuncSetAttribute((void*)wgemm<EPI_RSUB>,  cudaFuncAttributeMaxDynamicSharedMemorySize, SMEM_BYTES);
    cudaFuncSetAttribute((void*)wgemm<EPI_FISTA>, cudaFuncAttributeMaxDynamicSharedMemorySize, SMEM_BYTES);
    cudaFuncSetAttribute((void*)wgemm<EPI_ADD>,   cudaFuncAttributeMaxDynamicSharedMemorySize, SMEM_BYTES);

    // host-side FISTA momentum (data-independent): betas[k] consumed as
    // beta_{k+1} by the fused v-update at the end of step k (validated R5/R7)
    float betas[KSTEPS + 1];
    {
        float t = 1.0f; betas[0] = 0.0f;
        for (int k = 1; k <= KSTEPS; k++) {
            float tn = 0.5f * (1.0f + sqrtf(1.0f + 4.0f * t * t));
            betas[k] = (t - 1.0f) / tn;
            t = tn;
        }
    }

    // ---- prep -----------------------------------------------------------------
    auto rounds = [&](const float* s, fp16* o, size_t n) {
        int n4 = (int)(n / 4);
        round_kernel<<<(n4 + 255) / 256, 256>>>((const float4*)s, o, n4);
    };
    rounds(x,    xs, (size_t)BATCH * PDIM);
    rounds(A,    aa, (size_t)MMDIM * NCODE);
    rounds(Mmat, mw, (size_t)MMDIM * NOUTD);
    rounds(Psi,  ps, (size_t)NOUTD * NCODE);
    tround_kernel<<<dim3(H1DIM / 32, PDIM / 32),  dim3(32, 8)>>>(W1, w1, PDIM,  H1DIM);
    tround_kernel<<<dim3(H2DIM / 32, H1DIM / 32), dim3(32, 8)>>>(W2, w2, H1DIM, H2DIM);
    tround_kernel<<<dim3(NOUTD / 32, H2DIM / 32), dim3(32, 8)>>>(W3, w3, H2DIM, NOUTD);
    tround_kernel<<<dim3(NCODE / 32, MMDIM / 32), dim3(32, 8)>>>(A,  at, MMDIM, NCODE);

    const dim3 blk(256);
#define GRID(N) dim3((N) / 128, BATCH / 128)

    // ---- background MLP -----------------------------------------------------
    wgemm<EPI_GELU><<<GRID(H1DIM), blk, SMEM_BYTES>>>(
        xs, w1, H1DIM, PDIM, nullptr, h1,
        b1, nullptr, nullptr, nullptr, nullptr, nullptr, nullptr, 0, 0.f);
    wgemm<EPI_GELU><<<GRID(H2DIM), blk, SMEM_BYTES>>>(
        h1, w2, H2DIM, H1DIM, nullptr, h2,
        b2, nullptr, nullptr, nullptr, nullptr, nullptr, nullptr, 0, 0.f);
    wgemm<EPI_YBG><<<GRID(NOUTD), blk, SMEM_BYTES>>>(
        h2, w3, NOUTD, H2DIM, o_ybg, yb,
        b3, nullptr, nullptr, nullptr, nullptr, nullptr, nullptr, 0, 0.f);

    // ---- z = b - y_bg @ M^T  (writes fp32 z output + fp16 zh) ----------------
    wgemm<EPI_ZSUB><<<GRID(MMDIM), blk, SMEM_BYTES>>>(
        yb, mw, MMDIM, NOUTD, o_z, zh,
        bvec, nullptr, nullptr, nullptr, nullptr, nullptr, nullptr, 0, 0.f);

    // ---- FISTA loop -----------------------------------------------------------
    // step 0: v0 = 0 -> r0 = -z (sign flip, no GEMM)
    {
        int n2 = (BATCH * MMDIM) / 2;
        negh_kernel<<<(n2 + 255) / 256, 256>>>((const uint32_t*)zh, (uint32_t*)rs, n2);
    }
    for (int k = 0; k < KSTEPS; k++) {
        if (k > 0) {
            // r = v @ A^T - z  (fp16 out; fp16 z aux)
            wgemm<EPI_RSUB><<<GRID(MMDIM), blk, SMEM_BYTES>>>(
                vs, aa, MMDIM, NCODE, nullptr, rs,
                nullptr, zh, nullptr, nullptr, nullptr, nullptr, nullptr, 0, 0.f);
        }
        // alpha_new = soft(v - eta*(r @ A), eta*tau); v_next fused (fp32 state)
        wgemm<EPI_FISTA><<<GRID(NCODE), blk, SMEM_BYTES>>>(
            rs, at, NCODE, MMDIM, o_alpha, ap,
            nullptr, nullptr, vbuf, abuf, vs, leta, ltau, k, betas[k + 1]);
    }

    // ---- y_hat = y_bg + alpha @ Psi^T ----------------------------------------
    wgemm<EPI_ADD><<<GRID(NOUTD), blk, SMEM_BYTES>>>(
        ap, ps, NOUTD, NCODE, o_yhat, nullptr,
        o_ybg, nullptr, nullptr, nullptr, nullptr, nullptr, nullptr, 0, 0.f);
}

// round 10
// speedup vs baseline: 1.3597x; 1.3597x over previous
#include <cuda_runtime.h>
#include <cuda_fp16.h>
#include <math.h>
#include <stdint.h>

typedef __half fp16;

#define BATCH 8192
#define PDIM  512
#define H1DIM 1024
#define H2DIM 512
#define NOUTD 1024
#define MMDIM 512
#define NCODE 2048
#define KSTEPS 16

// ---------------- device scratch (no allocations allowed) -------------------
__device__ float g_v [(size_t)BATCH * NCODE];   // FISTA v (fp32 state)
__device__ float g_a0[(size_t)BATCH * NCODE];   // alpha (fp32 state)

// activations: single fp16 (GEMM inputs)
__device__ fp16 g_xs[(size_t)BATCH*PDIM];
__device__ fp16 g_h1[(size_t)BATCH*H1DIM];
__device__ fp16 g_h2[(size_t)BATCH*H2DIM];
__device__ fp16 g_yb[(size_t)BATCH*NOUTD];
__device__ fp16 g_vs[(size_t)BATCH*NCODE];
__device__ fp16 g_rs[(size_t)BATCH*MMDIM];
__device__ fp16 g_ap[(size_t)BATCH*NCODE];

// weights / operators: single fp16 (rounded once)
__device__ fp16 g_w1[(size_t)H1DIM*PDIM];    // W1^T
__device__ fp16 g_w2[(size_t)H2DIM*H1DIM];   // W2^T
__device__ fp16 g_w3[(size_t)NOUTD*H2DIM];   // W3^T
__device__ fp16 g_m [(size_t)MMDIM*NOUTD];   // M  (as stored)
__device__ fp16 g_aa[(size_t)MMDIM*NCODE];   // A  (as stored)
__device__ fp16 g_at[(size_t)NCODE*MMDIM];   // A^T
__device__ fp16 g_ps[(size_t)NOUTD*NCODE];   // Psi (as stored)

// ---------------- PTX helpers (legal on base compute_103 target) ------------
__device__ __forceinline__ uint32_t smem_u32(const void* p) {
    uint32_t a;
    asm("{ .reg .u64 t; cvta.to.shared.u64 t, %1; cvt.u32.u64 %0, t; }" : "=r"(a) : "l"(p));
    return a;
}
__device__ __forceinline__ void cp16(uint32_t d, const void* s) {
    asm volatile("cp.async.cg.shared.global [%0], [%1], 16;" :: "r"(d), "l"(s) : "memory");
}
#define CP_COMMIT() asm volatile("cp.async.commit_group;" ::: "memory")
#define CP_WAIT0()  asm volatile("cp.async.wait_group 0;" ::: "memory")

#define LDSM4(r0, r1, r2, r3, a) \
    asm volatile("ldmatrix.sync.aligned.m8n8.x4.shared.b16 {%0,%1,%2,%3}, [%4];" \
                 : "=r"(r0), "=r"(r1), "=r"(r2), "=r"(r3) : "r"(a))

#define MMA16816(c, a, b) \
    asm volatile("mma.sync.aligned.m16n8k16.row.col.f32.f16.f16.f32 " \
                 "{%0,%1,%2,%3}, {%4,%5,%6,%7}, {%8,%9}, {%0,%1,%2,%3};" \
                 : "+f"((c)[0]), "+f"((c)[1]), "+f"((c)[2]), "+f"((c)[3]) \
                 : "r"((a)[0]), "r"((a)[1]), "r"((a)[2]), "r"((a)[3]), \
                   "r"((b)[0]), "r"((b)[1]))

// ---------------- GEMM constants ---------------------------------------------
// SMEM tile: 128 rows x 64 fp16, padded row stride 72 fp16 = 144 B
// (9x16B -> conflict-free ldmatrix phases).
#define ROW_B   144
#define TILE_B  (128 * ROW_B)            // 18432 B per operand tile
#define STAGE_B (2 * TILE_B)             // A, B = 36864 B
#define SMEM_BYTES (2 * STAGE_B)         // 2 stages = 73728 B -> 2 CTAs/SM

enum { EPI_GELU = 0, EPI_YBG, EPI_ZSUB, EPI_RSUB, EPI_FISTA, EPI_ADD };

__device__ __forceinline__ float gelu_exact(float x) {
    return 0.5f * x * (1.0f + erff(x * 0.70710678118654752440f));
}
__device__ __forceinline__ void store2h(fp16* H, size_t idx, float o0, float o1) {
    *(__half2*)(H + idx) = __halves2half2(__float2half_rn(o0), __float2half_rn(o1));
}

// ---------------------------------------------------------------------------
// Warp-MMA GEMM: D[128x128 tile] = A[M,K] * (B[N,K])^T, fp32 acc, single fp16
// product, 2-stage cp.async double buffer, 2 CTAs/SM, fused epilogue.
// ---------------------------------------------------------------------------
template <int EPI>
__global__ void __launch_bounds__(256, 2)
wgemm(const fp16* __restrict__ Ag, const fp16* __restrict__ Bg,
      int Ndim, int Kdim,
      float* __restrict__ C0, fp16* __restrict__ Ch,
      const float* __restrict__ aux, const float* __restrict__ aux2,
      float* __restrict__ vout, fp16* __restrict__ vho,
      const float* __restrict__ leta, const float* __restrict__ ltau,
      int kidx, float beta)
{
    extern __shared__ char dyn[];
    const uint32_t sbase = smem_u32(dyn);

    const int tid = threadIdx.x;
    const int wid = tid >> 5;
    const int lid = tid & 31;
    const int m0  = blockIdx.y * 128;
    const int n0  = blockIdx.x * 128;
    const int m_w = (wid >> 2) * 64;     // warp m offset
    const int n_w = (wid & 3) * 32;      // warp n offset

    // ---- loader plan: 8 cp.async x 16B per thread per stage ------------------
    const fp16* gp[8];
    uint32_t so[8];
    {
        const fp16* srcs[2] = { Ag, Bg };
#pragma unroll
        for (int it = 0; it < 8; it++) {
            const int op  = it >> 2;                    // 0:A 1:B
            const int row = (it & 3) * 32 + (tid >> 3);
            const int seg = tid & 7;                    // 8 fp16 per 16B
            const int rb  = (op == 0) ? m0 : n0;
            gp[it] = srcs[op] + (size_t)(rb + row) * Kdim + seg * 8;
            so[it] = (uint32_t)(op * TILE_B + row * ROW_B + seg * 16);
        }
    }

    // ---- ldmatrix per-lane offsets -------------------------------------------
    const int aRow = (lid & 7) + ((lid >> 3) & 1) * 8;
    const int aK   = ((lid >> 4) & 1) * 8;
    const int bRow = (lid & 7) + ((lid >> 4) & 1) * 8;
    const int bK   = ((lid >> 3) & 1) * 8;
    const uint32_t aOff = (uint32_t)((m_w + aRow) * ROW_B + aK * 2);
    const uint32_t bOff = (uint32_t)((n_w + bRow) * ROW_B + bK * 2);

    float acc[4][4][4];
#pragma unroll
    for (int i = 0; i < 4; i++)
#pragma unroll
        for (int j = 0; j < 4; j++)
#pragma unroll
            for (int c = 0; c < 4; c++) acc[i][j][c] = 0.0f;

    const int S = Kdim >> 6;   // K-chunks of 64

    // prologue: stage 0 -> buf 0
#pragma unroll
    for (int it = 0; it < 8; it++) cp16(sbase + so[it], gp[it]);
    CP_COMMIT();

    for (int s = 0; s < S; s++) {
        CP_WAIT0();
        __syncthreads();
        if (s + 1 < S) {       // prefetch next stage (overlaps compute below)
            const uint32_t db = sbase + (uint32_t)(((s + 1) & 1) * STAGE_B);
            const int k0 = (s + 1) * 64;
#pragma unroll
            for (int it = 0; it < 8; it++) cp16(db + so[it], gp[it] + k0);
            CP_COMMIT();
        }
        const uint32_t st = sbase + (uint32_t)((s & 1) * STAGE_B);

#pragma unroll
        for (int kk = 0; kk < 4; kk++) {
            uint32_t ah[4][4], bh[4][2];
#pragma unroll
            for (int i = 0; i < 4; i++) {
                LDSM4(ah[i][0], ah[i][1], ah[i][2], ah[i][3],
                      st + aOff + i * (16 * ROW_B) + kk * 32);
            }
#pragma unroll
            for (int j = 0; j < 2; j++) {
                uint32_t r0, r1, r2, r3;
                LDSM4(r0, r1, r2, r3,
                      st + TILE_B + bOff + j * (16 * ROW_B) + kk * 32);
                bh[2 * j][0] = r0; bh[2 * j][1] = r1;
                bh[2 * j + 1][0] = r2; bh[2 * j + 1][1] = r3;
            }
#pragma unroll
            for (int i = 0; i < 4; i++)
#pragma unroll
                for (int j = 0; j < 4; j++)
                    MMA16816(acc[i][j], ah[i], bh[j]);
        }
    }

    // ---- fused epilogue -------------------------------------------------------
    float eta = 0.0f, thr = 0.0f;
    if (EPI == EPI_FISTA) {
        eta = expf(leta[kidx]);  eta = fminf(fmaxf(eta, 1e-8f), 10.0f);
        float tau = expf(ltau[kidx]); tau = fminf(fmaxf(tau, 1e-8f), 10.0f);
        thr = eta * tau;
    }

#pragma unroll
    for (int i = 0; i < 4; i++) {
#pragma unroll
        for (int j = 0; j < 4; j++) {
#pragma unroll
            for (int half = 0; half < 2; half++) {
                const int row = m0 + m_w + i * 16 + (lid >> 2) + half * 8;
                const int col = n0 + n_w + j * 8 + (lid & 3) * 2;
                const size_t idx = (size_t)row * Ndim + col;
                float o0 = acc[i][j][half * 2];
                float o1 = acc[i][j][half * 2 + 1];

                if (EPI == EPI_GELU) {
                    float2 bv = *(const float2*)&aux[col];
                    o0 = gelu_exact(o0 + bv.x);
                    o1 = gelu_exact(o1 + bv.y);
                    store2h(Ch, idx, o0, o1);
                } else if (EPI == EPI_YBG) {
                    float2 bv = *(const float2*)&aux[col];
                    o0 += bv.x; o1 += bv.y;
                    *(float2*)&C0[idx] = make_float2(o0, o1);
                    store2h(Ch, idx, o0, o1);
                } else if (EPI == EPI_ZSUB) {               // z = b - acc
                    float2 av = *(const float2*)&aux[idx];
                    *(float2*)&C0[idx] = make_float2(av.x - o0, av.y - o1);
                } else if (EPI == EPI_RSUB) {               // r = acc - z (fp16 out)
                    float2 av = *(const float2*)&aux[idx];
                    store2h(Ch, idx, o0 - av.x, o1 - av.y);
                } else if (EPI == EPI_FISTA) {
                    float2 vv = *(const float2*)&aux[idx];   // v (fp32)
                    float u0 = vv.x - eta * o0, u1 = vv.y - eta * o1;
                    float a0n = copysignf(fmaxf(fabsf(u0) - thr, 0.0f), u0);
                    float a1n = copysignf(fmaxf(fabsf(u1) - thr, 0.0f), u1);
                    if (vout) {
                        float2 ao = *(const float2*)&aux2[idx];  // alpha_old
                        float v0 = a0n + beta * (a0n - ao.x);
                        float v1 = a1n + beta * (a1n - ao.y);
                        *(float2*)&C0[idx]   = make_float2(a0n, a1n);
                        *(float2*)&vout[idx] = make_float2(v0, v1);
                        store2h(vho, idx, v0, v1);
                    } else {
                        *(float2*)&C0[idx] = make_float2(a0n, a1n);
                        store2h(Ch, idx, a0n, a1n);
                    }
                } else {                                    // EPI_ADD
                    float2 yv = *(const float2*)&aux[idx];
                    *(float2*)&C0[idx] = make_float2(o0 + yv.x, o1 + yv.y);
                }
            }
        }
    }
}

// ---------------- prep kernels ------------------------------------------------
__global__ void round_kernel(const float4* __restrict__ s, fp16* __restrict__ o, int n4)
{
    int i = blockIdx.x * blockDim.x + threadIdx.x;
    if (i < n4) {
        float4 v = s[i];
        size_t idx = (size_t)i * 4;
        *(__half2*)(o + idx)     = __halves2half2(__float2half_rn(v.x), __float2half_rn(v.y));
        *(__half2*)(o + idx + 2) = __halves2half2(__float2half_rn(v.z), __float2half_rn(v.w));
    }
}

// transpose + round: src [R,C] fp32 -> dst [C,R] fp16
__global__ void tround_kernel(const float* __restrict__ s, fp16* __restrict__ o,
                              int R, int C)
{
    __shared__ float t[32][33];
    const int bx = blockIdx.x * 32;   // C offset
    const int by = blockIdx.y * 32;   // R offset
    const int x = threadIdx.x, y = threadIdx.y;
#pragma unroll
    for (int i = 0; i < 4; i++)
        t[y + i * 8][x] = s[(size_t)(by + y + i * 8) * C + bx + x];
    __syncthreads();
#pragma unroll
    for (int i = 0; i < 4; i++)
        o[(size_t)(bx + y + i * 8) * R + by + x] = __float2half_rn(t[x][y + i * 8]);
}

__global__ void fill0_kernel(float4* __restrict__ p, int n4)
{
    int i = blockIdx.x * blockDim.x + threadIdx.x;
    if (i < n4) p[i] = make_float4(0.f, 0.f, 0.f, 0.f);
}

// ---------------------------------------------------------------------------
extern "C" void kernel_launch(void* const* d_in, const int* in_sizes, int n_in,
                              void* d_out, int out_size)
{
    const float* x    = (const float*)d_in[0];
    const float* bvec = (const float*)d_in[1];
    const float* W1   = (const float*)d_in[2];
    const float* b1   = (const float*)d_in[3];
    const float* W2   = (const float*)d_in[4];
    const float* b2   = (const float*)d_in[5];
    const float* W3   = (const float*)d_in[6];
    const float* b3   = (const float*)d_in[7];
    const float* A    = (const float*)d_in[8];
    const float* leta = (const float*)d_in[9];
    const float* ltau = (const float*)d_in[10];
    const float* Psi  = (const float*)d_in[11];
    const float* Mmat = (const float*)d_in[12];

    float* out     = (float*)d_out;
    float* o_ybg   = out;
    float* o_z     = o_ybg   + (size_t)BATCH * NOUTD;
    float* o_alpha = o_z     + (size_t)BATCH * MMDIM;
    float* o_yhat  = o_alpha + (size_t)BATCH * NCODE;

#define SYM(p, s) void* p##_; cudaGetSymbolAddress(&p##_, s); auto* p = (decltype(&s[0]))p##_
    SYM(vbuf, g_v);  SYM(abuf, g_a0);
    SYM(xs, g_xs);   SYM(h1, g_h1);   SYM(h2, g_h2);   SYM(yb, g_yb);
    SYM(vs, g_vs);   SYM(rs, g_rs);   SYM(ap, g_ap);
    SYM(w1, g_w1);   SYM(w2, g_w2);   SYM(w3, g_w3);
    SYM(mw, g_m);    SYM(aa, g_aa);   SYM(at, g_at);   SYM(ps, g_ps);
#undef SYM

    cudaFuncSetAttribute((void*)wgemm<EPI_GELU>,  cudaFuncAttributeMaxDynamicSharedMemorySize, SMEM_BYTES);
    cudaFuncSetAttribute((void*)wgemm<EPI_YBG>,   cudaFuncAttributeMaxDynamicSharedMemorySize, SMEM_BYTES);
    cudaFuncSetAttribute((void*)wgemm<EPI_ZSUB>,  cudaFuncAttributeMaxDynamicSharedMemorySize, SMEM_BYTES);
    cudaFuncSetAttribute((void*)wgemm<EPI_RSUB>,  cudaFuncAttributeMaxDynamicSharedMemorySize, SMEM_BYTES);
    cudaFuncSetAttribute((void*)wgemm<EPI_FISTA>, cudaFuncAttributeMaxDynamicSharedMemorySize, SMEM_BYTES);
    cudaFuncSetAttribute((void*)wgemm<EPI_ADD>,   cudaFuncAttributeMaxDynamicSharedMemorySize, SMEM_BYTES);

    // host-side FISTA momentum (data-independent)
    float betas[KSTEPS + 1];
    {
        float t = 1.0f; betas[0] = 0.0f;
        for (int k = 1; k <= KSTEPS; k++) {
            float tn = 0.5f * (1.0f + sqrtf(1.0f + 4.0f * t * t));
            betas[k] = (t - 1.0f) / tn;
            t = tn;
        }
    }

    // ---- prep -----------------------------------------------------------------
    auto rounds = [&](const float* s, fp16* o, size_t n) {
        int n4 = (int)(n / 4);
        round_kernel<<<(n4 + 255) / 256, 256>>>((const float4*)s, o, n4);
    };
    rounds(x,    xs, (size_t)BATCH * PDIM);
    rounds(A,    aa, (size_t)MMDIM * NCODE);
    rounds(Mmat, mw, (size_t)MMDIM * NOUTD);
    rounds(Psi,  ps, (size_t)NOUTD * NCODE);
    tround_kernel<<<dim3(H1DIM / 32, PDIM / 32),  dim3(32, 8)>>>(W1, w1, PDIM,  H1DIM);
    tround_kernel<<<dim3(H2DIM / 32, H1DIM / 32), dim3(32, 8)>>>(W2, w2, H1DIM, H2DIM);
    tround_kernel<<<dim3(NOUTD / 32, H2DIM / 32), dim3(32, 8)>>>(W3, w3, H2DIM, NOUTD);
    tround_kernel<<<dim3(NCODE / 32, MMDIM / 32), dim3(32, 8)>>>(A,  at, MMDIM, NCODE);

    const int nA = BATCH * NCODE;
    fill0_kernel<<<(nA / 4 + 255) / 256, 256>>>((float4*)vbuf, nA / 4);
    fill0_kernel<<<(nA / 4 + 255) / 256, 256>>>((float4*)abuf, nA / 4);
    fill0_kernel<<<(nA / 8 + 255) / 256, 256>>>((float4*)vs, nA / 8);

    const dim3 blk(256);
#define GRID(N) dim3((N) / 128, BATCH / 128)

    // ---- background MLP -----------------------------------------------------
    wgemm<EPI_GELU><<<GRID(H1DIM), blk, SMEM_BYTES>>>(
        xs, w1, H1DIM, PDIM, nullptr, h1,
        b1, nullptr, nullptr, nullptr, nullptr, nullptr, 0, 0.f);
    wgemm<EPI_GELU><<<GRID(H2DIM), blk, SMEM_BYTES>>>(
        h1, w2, H2DIM, H1DIM, nullptr, h2,
        b2, nullptr, nullptr, nullptr, nullptr, nullptr, 0, 0.f);
    wgemm<EPI_YBG><<<GRID(NOUTD), blk, SMEM_BYTES>>>(
        h2, w3, NOUTD, H2DIM, o_ybg, yb,
        b3, nullptr, nullptr, nullptr, nullptr, nullptr, 0, 0.f);

    // ---- z = b - y_bg @ M^T --------------------------------------------------
    wgemm<EPI_ZSUB><<<GRID(MMDIM), blk, SMEM_BYTES>>>(
        yb, mw, MMDIM, NOUTD, o_z, nullptr,
        bvec, nullptr, nullptr, nullptr, nullptr, nullptr, 0, 0.f);

    // ---- FISTA loop (v-momentum fused into EPI_FISTA epilogue) ---------------
    for (int k = 0; k < KSTEPS; k++) {
        // r = v @ A^T - z  (fp16 out)
        wgemm<EPI_RSUB><<<GRID(MMDIM), blk, SMEM_BYTES>>>(
            vs, aa, MMDIM, NCODE, nullptr, rs,
            o_z, nullptr, nullptr, nullptr, nullptr, nullptr, 0, 0.f);
        // alpha_new = soft(v - eta*(r @ A), eta*tau);  v_next fused
        if (k < KSTEPS - 1) {
            wgemm<EPI_FISTA><<<GRID(NCODE), blk, SMEM_BYTES>>>(
                rs, at, NCODE, MMDIM, abuf, nullptr,
                vbuf, abuf, vbuf, vs, leta, ltau, k, betas[k + 1]);
        } else {
            wgemm<EPI_FISTA><<<GRID(NCODE), blk, SMEM_BYTES>>>(
                rs, at, NCODE, MMDIM, o_alpha, ap,
                vbuf, abuf, nullptr, nullptr, leta, ltau, k, 0.f);
        }
    }

    // ---- y_hat = y_bg + alpha @ Psi^T ----------------------------------------
    wgemm<EPI_ADD><<<GRID(NOUTD), blk, SMEM_BYTES>>>(
        ap, ps, NOUTD, NCODE, o_yhat, nullptr,
        o_ybg, nullptr, nullptr, nullptr, nullptr, nullptr, 0, 0.f);
}

// round 11
// speedup vs baseline: 1.5313x; 1.1262x over previous
#include <cuda_runtime.h>
#include <cuda_fp16.h>
#include <math.h>
#include <stdint.h>

typedef __half fp16;

#define BATCH 8192
#define PDIM  512
#define H1DIM 1024
#define H2DIM 512
#define NOUTD 1024
#define MMDIM 512
#define NCODE 2048
#define KSTEPS 16

// ---------------- device scratch (no allocations allowed) -------------------
__device__ float g_aA[(size_t)BATCH * NCODE];   // alpha ping (fp32 state)
__device__ float g_aB[(size_t)BATCH * NCODE];   // alpha pong (fp32 state)

// activations: single fp16 (GEMM inputs)
__device__ fp16 g_xs[(size_t)BATCH*PDIM];
__device__ fp16 g_h1[(size_t)BATCH*H1DIM];
__device__ fp16 g_h2[(size_t)BATCH*H2DIM];
__device__ fp16 g_yb[(size_t)BATCH*NOUTD];
__device__ fp16 g_zh[(size_t)BATCH*MMDIM];   // z fp16 (RSUB aux)
__device__ fp16 g_vs[(size_t)BATCH*NCODE];   // v fp16 (r-GEMM input)
__device__ fp16 g_rs[(size_t)BATCH*MMDIM];   // r
__device__ fp16 g_ap[(size_t)BATCH*NCODE];   // final alpha fp16 (yhat input)

// weights / operators: single fp16 (rounded once)
__device__ fp16 g_w1[(size_t)H1DIM*PDIM];    // W1^T
__device__ fp16 g_w2[(size_t)H2DIM*H1DIM];   // W2^T
__device__ fp16 g_w3[(size_t)NOUTD*H2DIM];   // W3^T
__device__ fp16 g_m [(size_t)MMDIM*NOUTD];   // M
__device__ fp16 g_aa[(size_t)MMDIM*NCODE];   // A
__device__ fp16 g_at[(size_t)NCODE*MMDIM];   // A^T
__device__ fp16 g_ps[(size_t)NOUTD*NCODE];   // Psi

// ---------------- PTX helpers (legal on base compute_103 target) ------------
__device__ __forceinline__ uint32_t smem_u32(const void* p) {
    uint32_t a;
    asm("{ .reg .u64 t; cvta.to.shared.u64 t, %1; cvt.u32.u64 %0, t; }" : "=r"(a) : "l"(p));
    return a;
}
__device__ __forceinline__ void cp16(uint32_t d, const void* s) {
    asm volatile("cp.async.cg.shared.global [%0], [%1], 16;" :: "r"(d), "l"(s) : "memory");
}
#define CP_COMMIT() asm volatile("cp.async.commit_group;" ::: "memory")
#define CP_WAIT0()  asm volatile("cp.async.wait_group 0;" ::: "memory")

#define LDSM4(r0, r1, r2, r3, a) \
    asm volatile("ldmatrix.sync.aligned.m8n8.x4.shared.b16 {%0,%1,%2,%3}, [%4];" \
                 : "=r"(r0), "=r"(r1), "=r"(r2), "=r"(r3) : "r"(a))

#define MMA16816(c, a, b) \
    asm volatile("mma.sync.aligned.m16n8k16.row.col.f32.f16.f16.f32 " \
                 "{%0,%1,%2,%3}, {%4,%5,%6,%7}, {%8,%9}, {%0,%1,%2,%3};" \
                 : "+f"((c)[0]), "+f"((c)[1]), "+f"((c)[2]), "+f"((c)[3]) \
                 : "r"((a)[0]), "r"((a)[1]), "r"((a)[2]), "r"((a)[3]), \
                   "r"((b)[0]), "r"((b)[1]))

// ---------------- GEMM constants ---------------------------------------------
#define ROW_B   144
#define TILE_B  (128 * ROW_B)            // 18432 B per operand tile
#define STAGE_B (2 * TILE_B)             // A, B = 36864 B
#define SMEM_BYTES (2 * STAGE_B)         // 73728 B -> 2 CTAs/SM

enum { EPI_GELU = 0, EPI_YBG, EPI_ZSUB, EPI_RSUB,
       EPI_FISTA0, EPI_FISTAM, EPI_FISTAL, EPI_ADD };

__device__ __forceinline__ float gelu_exact(float x) {
    return 0.5f * x * (1.0f + erff(x * 0.70710678118654752440f));
}
__device__ __forceinline__ void store2h(fp16* H, size_t idx, float o0, float o1) {
    *(__half2*)(H + idx) = __halves2half2(__float2half_rn(o0), __float2half_rn(o1));
}
__device__ __forceinline__ float softf(float u, float thr) {
    return copysignf(fmaxf(fabsf(u) - thr, 0.0f), u);
}

// ---------------------------------------------------------------------------
// Warp-MMA GEMM: D[128x128 tile] = A[M,K] * (B[N,K])^T, fp32 acc, single fp16
// product, 2-stage cp.async double buffer, 2 CTAs/SM, fused epilogue.
// ---------------------------------------------------------------------------
template <int EPI>
__global__ void __launch_bounds__(256, 2)
wgemm(const fp16* __restrict__ Ag, const fp16* __restrict__ Bg,
      int Ndim, int Kdim,
      float* __restrict__ C0, fp16* __restrict__ Ch,
      const float* __restrict__ aux,   // bias / bvec / y_bg / alpha_cur
      const float* __restrict__ aux2,  // alpha_prev
      const fp16* __restrict__ auxH,   // zh for RSUB
      float* __restrict__ vout,        // fp32 alpha write target (FISTA0/M)
      fp16* __restrict__ vho,          // fp16 v shadow write (FISTA0/M)
      const float* __restrict__ leta, const float* __restrict__ ltau,
      int kidx, float betaV, float betaN)
{
    extern __shared__ char dyn[];
    const uint32_t sbase = smem_u32(dyn);

    const int tid = threadIdx.x;
    const int wid = tid >> 5;
    const int lid = tid & 31;
    const int m0  = blockIdx.y * 128;
    const int n0  = blockIdx.x * 128;
    const int m_w = (wid >> 2) * 64;
    const int n_w = (wid & 3) * 32;

    // ---- loader plan: 8 cp.async x 16B per thread per stage ------------------
    const fp16* gp[8];
    uint32_t so[8];
    {
        const fp16* srcs[2] = { Ag, Bg };
#pragma unroll
        for (int it = 0; it < 8; it++) {
            const int op  = it >> 2;                    // 0:A 1:B
            const int row = (it & 3) * 32 + (tid >> 3);
            const int seg = tid & 7;
            const int rb  = (op == 0) ? m0 : n0;
            gp[it] = srcs[op] + (size_t)(rb + row) * Kdim + seg * 8;
            so[it] = (uint32_t)(op * TILE_B + row * ROW_B + seg * 16);
        }
    }

    // ---- ldmatrix per-lane offsets -------------------------------------------
    const int aRow = (lid & 7) + ((lid >> 3) & 1) * 8;
    const int aK   = ((lid >> 4) & 1) * 8;
    const int bRow = (lid & 7) + ((lid >> 4) & 1) * 8;
    const int bK   = ((lid >> 3) & 1) * 8;
    const uint32_t aOff = (uint32_t)((m_w + aRow) * ROW_B + aK * 2);
    const uint32_t bOff = (uint32_t)((n_w + bRow) * ROW_B + bK * 2);

    float acc[4][4][4];
#pragma unroll
    for (int i = 0; i < 4; i++)
#pragma unroll
        for (int j = 0; j < 4; j++)
#pragma unroll
            for (int c = 0; c < 4; c++) acc[i][j][c] = 0.0f;

    const int S = Kdim >> 6;

#pragma unroll
    for (int it = 0; it < 8; it++) cp16(sbase + so[it], gp[it]);
    CP_COMMIT();

    for (int s = 0; s < S; s++) {
        CP_WAIT0();
        __syncthreads();
        if (s + 1 < S) {
            const uint32_t db = sbase + (uint32_t)(((s + 1) & 1) * STAGE_B);
            const int k0 = (s + 1) * 64;
#pragma unroll
            for (int it = 0; it < 8; it++) cp16(db + so[it], gp[it] + k0);
            CP_COMMIT();
        }
        const uint32_t st = sbase + (uint32_t)((s & 1) * STAGE_B);

#pragma unroll
        for (int kk = 0; kk < 4; kk++) {
            uint32_t ah[4][4], bh[4][2];
#pragma unroll
            for (int i = 0; i < 4; i++) {
                LDSM4(ah[i][0], ah[i][1], ah[i][2], ah[i][3],
                      st + aOff + i * (16 * ROW_B) + kk * 32);
            }
#pragma unroll
            for (int j = 0; j < 2; j++) {
                uint32_t r0, r1, r2, r3;
                LDSM4(r0, r1, r2, r3,
                      st + TILE_B + bOff + j * (16 * ROW_B) + kk * 32);
                bh[2 * j][0] = r0; bh[2 * j][1] = r1;
                bh[2 * j + 1][0] = r2; bh[2 * j + 1][1] = r3;
            }
#pragma unroll
            for (int i = 0; i < 4; i++)
#pragma unroll
                for (int j = 0; j < 4; j++)
                    MMA16816(acc[i][j], ah[i], bh[j]);
        }
    }

    // ---- fused epilogue -------------------------------------------------------
    const bool FIST = (EPI == EPI_FISTA0 || EPI == EPI_FISTAM || EPI == EPI_FISTAL);
    float eta = 0.0f, thr = 0.0f;
    if (FIST) {
        eta = expf(leta[kidx]);  eta = fminf(fmaxf(eta, 1e-8f), 10.0f);
        float tau = expf(ltau[kidx]); tau = fminf(fmaxf(tau, 1e-8f), 10.0f);
        thr = eta * tau;
    }

#pragma unroll
    for (int i = 0; i < 4; i++) {
#pragma unroll
        for (int j = 0; j < 4; j++) {
#pragma unroll
            for (int half = 0; half < 2; half++) {
                const int row = m0 + m_w + i * 16 + (lid >> 2) + half * 8;
                const int col = n0 + n_w + j * 8 + (lid & 3) * 2;
                const size_t idx = (size_t)row * Ndim + col;
                float o0 = acc[i][j][half * 2];
                float o1 = acc[i][j][half * 2 + 1];

                if (EPI == EPI_GELU) {
                    float2 bv = *(const float2*)&aux[col];
                    o0 = gelu_exact(o0 + bv.x);
                    o1 = gelu_exact(o1 + bv.y);
                    store2h(Ch, idx, o0, o1);
                } else if (EPI == EPI_YBG) {
                    float2 bv = *(const float2*)&aux[col];
                    o0 += bv.x; o1 += bv.y;
                    *(float2*)&C0[idx] = make_float2(o0, o1);
                    store2h(Ch, idx, o0, o1);
                } else if (EPI == EPI_ZSUB) {               // z = b - acc (+ zh)
                    float2 av = *(const float2*)&aux[idx];
                    float z0 = av.x - o0, z1 = av.y - o1;
                    *(float2*)&C0[idx] = make_float2(z0, z1);
                    store2h(Ch, idx, z0, z1);
                } else if (EPI == EPI_RSUB) {               // r = acc - z (fp16 aux)
                    __half2 zv = *(const __half2*)&auxH[idx];
                    store2h(Ch, idx, o0 - __half2float(__low2half(zv)),
                                     o1 - __half2float(__high2half(zv)));
                } else if (EPI == EPI_FISTA0) {             // k=0: v=0
                    float a0n = softf(-eta * o0, thr);
                    float a1n = softf(-eta * o1, thr);
                    *(float2*)&vout[idx] = make_float2(a0n, a1n);
                    store2h(vho, idx, a0n, a1n);            // v_1 = alpha_1 (beta1=0)
                } else if (EPI == EPI_FISTAM) {
                    float2 ac = *(const float2*)&aux[idx];  // alpha_k
                    float2 ap = *(const float2*)&aux2[idx]; // alpha_{k-1}
                    float v0 = ac.x + betaV * (ac.x - ap.x);
                    float v1 = ac.y + betaV * (ac.y - ap.y);
                    float a0n = softf(v0 - eta * o0, thr);
                    float a1n = softf(v1 - eta * o1, thr);
                    float vn0 = a0n + betaN * (a0n - ac.x);
                    float vn1 = a1n + betaN * (a1n - ac.y);
                    *(float2*)&vout[idx] = make_float2(a0n, a1n);   // -> prev buf
                    store2h(vho, idx, vn0, vn1);
                } else if (EPI == EPI_FISTAL) {             // last step
                    float2 ac = *(const float2*)&aux[idx];
                    float2 ap = *(const float2*)&aux2[idx];
                    float v0 = ac.x + betaV * (ac.x - ap.x);
                    float v1 = ac.y + betaV * (ac.y - ap.y);
                    float a0n = softf(v0 - eta * o0, thr);
                    float a1n = softf(v1 - eta * o1, thr);
                    *(float2*)&C0[idx] = make_float2(a0n, a1n);     // o_alpha
                    store2h(Ch, idx, a0n, a1n);                      // ap fp16
                } else {                                    // EPI_ADD: yhat
                    float2 yv = *(const float2*)&aux[idx];
                    *(float2*)&C0[idx] = make_float2(o0 + yv.x, o1 + yv.y);
                }
            }
        }
    }
}

// ---------------- prep kernels ------------------------------------------------
__global__ void round_kernel(const float4* __restrict__ s, fp16* __restrict__ o, int n4)
{
    int i = blockIdx.x * blockDim.x + threadIdx.x;
    if (i < n4) {
        float4 v = s[i];
        size_t idx = (size_t)i * 4;
        *(__half2*)(o + idx)     = __halves2half2(__float2half_rn(v.x), __float2half_rn(v.y));
        *(__half2*)(o + idx + 2) = __halves2half2(__float2half_rn(v.z), __float2half_rn(v.w));
    }
}

// transpose + round: src [R,C] fp32 -> dst [C,R] fp16
__global__ void tround_kernel(const float* __restrict__ s, fp16* __restrict__ o,
                              int R, int C)
{
    __shared__ float t[32][33];
    const int bx = blockIdx.x * 32;
    const int by = blockIdx.y * 32;
    const int x = threadIdx.x, y = threadIdx.y;
#pragma unroll
    for (int i = 0; i < 4; i++)
        t[y + i * 8][x] = s[(size_t)(by + y + i * 8) * C + bx + x];
    __syncthreads();
#pragma unroll
    for (int i = 0; i < 4; i++)
        o[(size_t)(bx + y + i * 8) * R + by + x] = __float2half_rn(t[x][y + i * 8]);
}

// r0 = -z  (flip fp16 sign bits pairwise)
__global__ void negh_kernel(const uint32_t* __restrict__ s, uint32_t* __restrict__ d, int n2)
{
    int i = blockIdx.x * blockDim.x + threadIdx.x;
    if (i < n2) d[i] = s[i] ^ 0x80008000u;
}

// ---------------------------------------------------------------------------
extern "C" void kernel_launch(void* const* d_in, const int* in_sizes, int n_in,
                              void* d_out, int out_size)
{
    const float* x    = (const float*)d_in[0];
    const float* bvec = (const float*)d_in[1];
    const float* W1   = (const float*)d_in[2];
    const float* b1   = (const float*)d_in[3];
    const float* W2   = (const float*)d_in[4];
    const float* b2   = (const float*)d_in[5];
    const float* W3   = (const float*)d_in[6];
    const float* b3   = (const float*)d_in[7];
    const float* A    = (const float*)d_in[8];
    const float* leta = (const float*)d_in[9];
    const float* ltau = (const float*)d_in[10];
    const float* Psi  = (const float*)d_in[11];
    const float* Mmat = (const float*)d_in[12];

    float* out     = (float*)d_out;
    float* o_ybg   = out;
    float* o_z     = o_ybg   + (size_t)BATCH * NOUTD;
    float* o_alpha = o_z     + (size_t)BATCH * MMDIM;
    float* o_yhat  = o_alpha + (size_t)BATCH * NCODE;

#define SYM(p, s) void* p##_; cudaGetSymbolAddress(&p##_, s); auto* p = (decltype(&s[0]))p##_
    SYM(aA, g_aA);   SYM(aB, g_aB);
    SYM(xs, g_xs);   SYM(h1, g_h1);   SYM(h2, g_h2);   SYM(yb, g_yb);
    SYM(zh, g_zh);   SYM(vs, g_vs);   SYM(rs, g_rs);   SYM(ap, g_ap);
    SYM(w1, g_w1);   SYM(w2, g_w2);   SYM(w3, g_w3);
    SYM(mw, g_m);    SYM(aa, g_aa);   SYM(at, g_at);   SYM(ps, g_ps);
#undef SYM

    cudaFuncSetAttribute((void*)wgemm<EPI_GELU>,   cudaFuncAttributeMaxDynamicSharedMemorySize, SMEM_BYTES);
    cudaFuncSetAttribute((void*)wgemm<EPI_YBG>,    cudaFuncAttributeMaxDynamicSharedMemorySize, SMEM_BYTES);
    cudaFuncSetAttribute((void*)wgemm<EPI_ZSUB>,   cudaFuncAttributeMaxDynamicSharedMemorySize, SMEM_BYTES);
    cudaFuncSetAttribute((void*)wgemm<EPI_RSUB>,   cudaFuncAttributeMaxDynamicSharedMemorySize, SMEM_BYTES);
    cudaFuncSetAttribute((void*)wgemm<EPI_FISTA0>, cudaFuncAttributeMaxDynamicSharedMemorySize, SMEM_BYTES);
    cudaFuncSetAttribute((void*)wgemm<EPI_FISTAM>, cudaFuncAttributeMaxDynamicSharedMemorySize, SMEM_BYTES);
    cudaFuncSetAttribute((void*)wgemm<EPI_FISTAL>, cudaFuncAttributeMaxDynamicSharedMemorySize, SMEM_BYTES);
    cudaFuncSetAttribute((void*)wgemm<EPI_ADD>,    cudaFuncAttributeMaxDynamicSharedMemorySize, SMEM_BYTES);

    // host-side FISTA momentum (data-independent): betas[k] = beta used to
    // FORM v_k from alpha_k, alpha_{k-1} (betas[1] = 0; validated R5/R7/R10)
    float betas[KSTEPS + 1];
    {
        float t = 1.0f; betas[0] = 0.0f;
        for (int k = 1; k <= KSTEPS; k++) {
            float tn = 0.5f * (1.0f + sqrtf(1.0f + 4.0f * t * t));
            betas[k] = (t - 1.0f) / tn;
            t = tn;
        }
    }

    // ---- prep -----------------------------------------------------------------
    auto rounds = [&](const float* s, fp16* o, size_t n) {
        int n4 = (int)(n / 4);
        round_kernel<<<(n4 + 255) / 256, 256>>>((const float4*)s, o, n4);
    };
    rounds(x,    xs, (size_t)BATCH * PDIM);
    rounds(A,    aa, (size_t)MMDIM * NCODE);
    rounds(Mmat, mw, (size_t)MMDIM * NOUTD);
    rounds(Psi,  ps, (size_t)NOUTD * NCODE);
    tround_kernel<<<dim3(H1DIM / 32, PDIM / 32),  dim3(32, 8)>>>(W1, w1, PDIM,  H1DIM);
    tround_kernel<<<dim3(H2DIM / 32, H1DIM / 32), dim3(32, 8)>>>(W2, w2, H1DIM, H2DIM);
    tround_kernel<<<dim3(NOUTD / 32, H2DIM / 32), dim3(32, 8)>>>(W3, w3, H2DIM, NOUTD);
    tround_kernel<<<dim3(NCODE / 32, MMDIM / 32), dim3(32, 8)>>>(A,  at, MMDIM, NCODE);

    const dim3 blk(256);
#define GRID(N) dim3((N) / 128, BATCH / 128)
#define NUL0 (float*)nullptr
#define NULH (fp16*)nullptr

    // ---- background MLP -----------------------------------------------------
    wgemm<EPI_GELU><<<GRID(H1DIM), blk, SMEM_BYTES>>>(
        xs, w1, H1DIM, PDIM, NUL0, h1, b1, NUL0, NULH, NUL0, NULH,
        NUL0, NUL0, 0, 0.f, 0.f);
    wgemm<EPI_GELU><<<GRID(H2DIM), blk, SMEM_BYTES>>>(
        h1, w2, H2DIM, H1DIM, NUL0, h2, b2, NUL0, NULH, NUL0, NULH,
        NUL0, NUL0, 0, 0.f, 0.f);
    wgemm<EPI_YBG><<<GRID(NOUTD), blk, SMEM_BYTES>>>(
        h2, w3, NOUTD, H2DIM, o_ybg, yb, b3, NUL0, NULH, NUL0, NULH,
        NUL0, NUL0, 0, 0.f, 0.f);

    // ---- z = b - y_bg @ M^T  (fp32 z output + fp16 zh) ------------------------
    wgemm<EPI_ZSUB><<<GRID(MMDIM), blk, SMEM_BYTES>>>(
        yb, mw, MMDIM, NOUTD, o_z, zh, bvec, NUL0, NULH, NUL0, NULH,
        NUL0, NUL0, 0, 0.f, 0.f);

    // ---- FISTA loop -----------------------------------------------------------
    // step 0: v0 = 0 -> r0 = -z (sign flip; no GEMM, no fills)
    {
        int n2 = (BATCH * MMDIM) / 2;
        negh_kernel<<<(n2 + 255) / 256, 256>>>((const uint32_t*)zh, (uint32_t*)rs, n2);
    }
    // alpha_1 = soft(-eta0*grad0);  vs = fp16(alpha_1)  (beta1 = 0)
    wgemm<EPI_FISTA0><<<GRID(NCODE), blk, SMEM_BYTES>>>(
        rs, at, NCODE, MMDIM, NUL0, NULH, NUL0, NUL0, NULH,
        aA, vs, leta, ltau, 0, 0.f, 0.f);

    float* cur  = aA;   // alpha_k
    float* prev = aB;   // alpha_{k-1}  (k=1: aliased to cur; betaV=0 nulls it)
    for (int k = 1; k < KSTEPS; k++) {
        // r = v @ A^T - z
        wgemm<EPI_RSUB><<<GRID(MMDIM), blk, SMEM_BYTES>>>(
            vs, aa, MMDIM, NCODE, NUL0, rs, NUL0, NUL0, zh, NUL0, NULH,
            NUL0, NUL0, 0, 0.f, 0.f);
        const float* pv = (k == 1) ? cur : prev;    // betas[1]=0 -> prev unused
        if (k < KSTEPS - 1) {
            float* dst = (k == 1) ? aB : prev;      // write alpha_{k+1}
            wgemm<EPI_FISTAM><<<GRID(NCODE), blk, SMEM_BYTES>>>(
                rs, at, NCODE, MMDIM, NUL0, NULH, cur, pv, NULH,
                dst, vs, leta, ltau, k, betas[k], betas[k + 1]);
            prev = cur; cur = dst;
        } else {
            wgemm<EPI_FISTAL><<<GRID(NCODE), blk, SMEM_BYTES>>>(
                rs, at, NCODE, MMDIM, o_alpha, ap, cur, pv, NULH,
                NUL0, NULH, leta, ltau, k, betas[k], 0.f);
        }
    }

    // ---- y_hat = y_bg + alpha @ Psi^T ----------------------------------------
    wgemm<EPI_ADD><<<GRID(NOUTD), blk, SMEM_BYTES>>>(
        ap, ps, NOUTD, NCODE, o_yhat, NULH, o_ybg, NUL0, NULH, NUL0, NULH,
        NUL0, NUL0, 0, 0.f, 0.f);
}

// round 12
// speedup vs baseline: 1.5498x; 1.0121x over previous
#include <cuda_runtime.h>
#include <cuda_fp16.h>
#include <math.h>
#include <stdint.h>

typedef __half fp16;

#define BATCH 8192
#define PDIM  512
#define H1DIM 1024
#define H2DIM 512
#define NOUTD 1024
#define MMDIM 512
#define NCODE 2048
#define KSTEPS 16

// ---------------- device scratch (no allocations allowed) -------------------
__device__ float g_aA[(size_t)BATCH * NCODE];   // alpha ping (fp32 state)
__device__ float g_aB[(size_t)BATCH * NCODE];   // alpha pong (fp32 state)
__device__ int   g_cnt[KSTEPS * 64];            // per-step per-mstrip counters

__device__ fp16 g_xs[(size_t)BATCH*PDIM];
__device__ fp16 g_h1[(size_t)BATCH*H1DIM];
__device__ fp16 g_h2[(size_t)BATCH*H2DIM];
__device__ fp16 g_yb[(size_t)BATCH*NOUTD];
__device__ fp16 g_zh[(size_t)BATCH*MMDIM];   // z fp16
__device__ fp16 g_vs[(size_t)BATCH*NCODE];   // v fp16 (GEMM input)
__device__ fp16 g_rs[(size_t)BATCH*MMDIM];   // r
__device__ fp16 g_ap[(size_t)BATCH*NCODE];   // final alpha fp16

__device__ fp16 g_w1[(size_t)H1DIM*PDIM];    // W1^T
__device__ fp16 g_w2[(size_t)H2DIM*H1DIM];   // W2^T
__device__ fp16 g_w3[(size_t)NOUTD*H2DIM];   // W3^T
__device__ fp16 g_m [(size_t)MMDIM*NOUTD];   // M
__device__ fp16 g_aa[(size_t)MMDIM*NCODE];   // A
__device__ fp16 g_at[(size_t)NCODE*MMDIM];   // A^T
__device__ fp16 g_ps[(size_t)NOUTD*NCODE];   // Psi

// ---------------- PTX helpers -------------------------------------------------
__device__ __forceinline__ uint32_t smem_u32(const void* p) {
    uint32_t a;
    asm("{ .reg .u64 t; cvta.to.shared.u64 t, %1; cvt.u32.u64 %0, t; }" : "=r"(a) : "l"(p));
    return a;
}
__device__ __forceinline__ void cp16(uint32_t d, const void* s) {
    asm volatile("cp.async.cg.shared.global [%0], [%1], 16;" :: "r"(d), "l"(s) : "memory");
}
#define CP_COMMIT() asm volatile("cp.async.commit_group;" ::: "memory")
#define CP_WAIT0()  asm volatile("cp.async.wait_group 0;" ::: "memory")

#define LDSM4(r0, r1, r2, r3, a) \
    asm volatile("ldmatrix.sync.aligned.m8n8.x4.shared.b16 {%0,%1,%2,%3}, [%4];" \
                 : "=r"(r0), "=r"(r1), "=r"(r2), "=r"(r3) : "r"(a))

#define MMA16816(c, a, b) \
    asm volatile("mma.sync.aligned.m16n8k16.row.col.f32.f16.f16.f32 " \
                 "{%0,%1,%2,%3}, {%4,%5,%6,%7}, {%8,%9}, {%0,%1,%2,%3};" \
                 : "+f"((c)[0]), "+f"((c)[1]), "+f"((c)[2]), "+f"((c)[3]) \
                 : "r"((a)[0]), "r"((a)[1]), "r"((a)[2]), "r"((a)[3]), \
                   "r"((b)[0]), "r"((b)[1]))

// CTA dependency wait/signal (producers all resident in wave 1 -> no deadlock)
__device__ __forceinline__ void ctawait(const int* p, int tgt) {
    if (threadIdx.x == 0) {
        const volatile int* vp = (const volatile int*)p;
        while (*vp < tgt) __nanosleep(64);
        __threadfence();
    }
    __syncthreads();
}
__device__ __forceinline__ void ctasignal(int* p) {
    __syncthreads();
    if (threadIdx.x == 0) {
        __threadfence();
        atomicAdd(p, 1);
    }
}

// ---------------- GEMM constants ---------------------------------------------
#define ROW_B   144
#define TILE_B  (128 * ROW_B)            // 18432 B
#define STAGE_B (2 * TILE_B)             // 36864 B
#define SMEM_BYTES (2 * STAGE_B)         // 73728 B -> 2 CTAs/SM

enum { EPI_GELU = 0, EPI_YBG, EPI_ZSUB, EPI_ADD };

__device__ __forceinline__ float gelu_exact(float x) {
    return 0.5f * x * (1.0f + erff(x * 0.70710678118654752440f));
}
__device__ __forceinline__ void store2h(fp16* H, size_t idx, float o0, float o1) {
    *(__half2*)(H + idx) = __halves2half2(__float2half_rn(o0), __float2half_rn(o1));
}
__device__ __forceinline__ float softf(float u, float thr) {
    return copysignf(fmaxf(fabsf(u) - thr, 0.0f), u);
}

// ---- shared GEMM mainloop (A[M,K] * B[N,K]^T, fp16, fp32 acc) ----------------
#define GEMM_MAINLOOP(Ag, Bg, Kdim)                                            \
    const fp16* gp[8];                                                          \
    uint32_t so[8];                                                             \
    {                                                                           \
        const fp16* srcs[2] = { (Ag), (Bg) };                                   \
        _Pragma("unroll")                                                       \
        for (int it = 0; it < 8; it++) {                                        \
            const int op  = it >> 2;                                            \
            const int row = (it & 3) * 32 + (tid >> 3);                         \
            const int seg = tid & 7;                                            \
            const int rb  = (op == 0) ? m0 : n0;                                \
            gp[it] = srcs[op] + (size_t)(rb + row) * (Kdim) + seg * 8;          \
            so[it] = (uint32_t)(op * TILE_B + row * ROW_B + seg * 16);          \
        }                                                                       \
    }                                                                           \
    _Pragma("unroll")                                                           \
    for (int it = 0; it < 8; it++) cp16(sbase + so[it], gp[it]);                \
    CP_COMMIT();                                                                \
    const int S = (Kdim) >> 6;                                                  \
    for (int s = 0; s < S; s++) {                                               \
        CP_WAIT0();                                                             \
        __syncthreads();                                                        \
        if (s + 1 < S) {                                                        \
            const uint32_t db = sbase + (uint32_t)(((s + 1) & 1) * STAGE_B);    \
            const int k0 = (s + 1) * 64;                                        \
            _Pragma("unroll")                                                   \
            for (int it = 0; it < 8; it++) cp16(db + so[it], gp[it] + k0);      \
            CP_COMMIT();                                                        \
        }                                                                       \
        const uint32_t st = sbase + (uint32_t)((s & 1) * STAGE_B);              \
        _Pragma("unroll")                                                       \
        for (int kk = 0; kk < 4; kk++) {                                        \
            uint32_t ah[4][4], bh[4][2];                                        \
            _Pragma("unroll")                                                   \
            for (int i = 0; i < 4; i++)                                         \
                LDSM4(ah[i][0], ah[i][1], ah[i][2], ah[i][3],                   \
                      st + aOff + i * (16 * ROW_B) + kk * 32);                  \
            _Pragma("unroll")                                                   \
            for (int j = 0; j < 2; j++) {                                       \
                uint32_t r0, r1, r2, r3;                                        \
                LDSM4(r0, r1, r2, r3,                                           \
                      st + TILE_B + bOff + j * (16 * ROW_B) + kk * 32);         \
                bh[2 * j][0] = r0; bh[2 * j][1] = r1;                           \
                bh[2 * j + 1][0] = r2; bh[2 * j + 1][1] = r3;                   \
            }                                                                   \
            _Pragma("unroll")                                                   \
            for (int i = 0; i < 4; i++)                                         \
                _Pragma("unroll")                                               \
                for (int j = 0; j < 4; j++)                                     \
                    MMA16816(acc[i][j], ah[i], bh[j]);                          \
        }                                                                       \
    }

// ---------------------------------------------------------------------------
// wgemm: standalone GEMM for MLP / z / yhat phases.
// ---------------------------------------------------------------------------
template <int EPI>
__global__ void __launch_bounds__(256, 2)
wgemm(const fp16* __restrict__ Ag, const fp16* __restrict__ Bg,
      int Ndim, int Kdim,
      float* __restrict__ C0, fp16* __restrict__ Ch,
      const float* __restrict__ aux)
{
    extern __shared__ char dyn[];
    const uint32_t sbase = smem_u32(dyn);
    const int tid = threadIdx.x;
    const int wid = tid >> 5;
    const int lid = tid & 31;
    const int m0  = blockIdx.y * 128;
    const int n0  = blockIdx.x * 128;
    const int m_w = (wid >> 2) * 64;
    const int n_w = (wid & 3) * 32;

    const int aRow = (lid & 7) + ((lid >> 3) & 1) * 8;
    const int aK   = ((lid >> 4) & 1) * 8;
    const int bRow = (lid & 7) + ((lid >> 4) & 1) * 8;
    const int bK   = ((lid >> 3) & 1) * 8;
    const uint32_t aOff = (uint32_t)((m_w + aRow) * ROW_B + aK * 2);
    const uint32_t bOff = (uint32_t)((n_w + bRow) * ROW_B + bK * 2);

    float acc[4][4][4];
#pragma unroll
    for (int i = 0; i < 4; i++)
#pragma unroll
        for (int j = 0; j < 4; j++)
#pragma unroll
            for (int c = 0; c < 4; c++) acc[i][j][c] = 0.0f;

    GEMM_MAINLOOP(Ag, Bg, Kdim)

#pragma unroll
    for (int i = 0; i < 4; i++)
#pragma unroll
        for (int j = 0; j < 4; j++)
#pragma unroll
            for (int half = 0; half < 2; half++) {
                const int row = m0 + m_w + i * 16 + (lid >> 2) + half * 8;
                const int col = n0 + n_w + j * 8 + (lid & 3) * 2;
                const size_t idx = (size_t)row * Ndim + col;
                float o0 = acc[i][j][half * 2];
                float o1 = acc[i][j][half * 2 + 1];
                if (EPI == EPI_GELU) {
                    float2 bv = *(const float2*)&aux[col];
                    store2h(Ch, idx, gelu_exact(o0 + bv.x), gelu_exact(o1 + bv.y));
                } else if (EPI == EPI_YBG) {
                    float2 bv = *(const float2*)&aux[col];
                    o0 += bv.x; o1 += bv.y;
                    *(float2*)&C0[idx] = make_float2(o0, o1);
                    store2h(Ch, idx, o0, o1);
                } else if (EPI == EPI_ZSUB) {
                    float2 av = *(const float2*)&aux[idx];
                    float z0 = av.x - o0, z1 = av.y - o1;
                    *(float2*)&C0[idx] = make_float2(z0, z1);
                    store2h(Ch, idx, z0, z1);
                } else {                                    // EPI_ADD
                    float2 yv = *(const float2*)&aux[idx];
                    *(float2*)&C0[idx] = make_float2(o0 + yv.x, o1 + yv.y);
                }
            }
}

// ---------------------------------------------------------------------------
// fstep: one fused FISTA step. Grid = 1280 CTAs:
//   bid <  256 : r-tile  (r = v@A^T - z ; MODE 0: r = -z copy)  -> signal cnt[mt]
//   bid >= 256 : alpha-tile, waits cnt[mt]==4, then alpha GEMM + FISTA epilogue
// MODE: 0 = first step (v=0), 1 = middle, 2 = last.
// ---------------------------------------------------------------------------
template <int MODE>
__global__ void __launch_bounds__(256, 2)
fstep(const fp16* __restrict__ Baa, const fp16* __restrict__ Bat,
      const fp16* __restrict__ zh,  fp16* __restrict__ rsb,
      fp16* __restrict__ vsb,
      const float* __restrict__ acur, const float* __restrict__ aprev,
      float* __restrict__ adst,
      float* __restrict__ oalpha, fp16* __restrict__ apo,
      const float* __restrict__ leta, const float* __restrict__ ltau,
      int kidx, float betaV, float betaN, int* __restrict__ cnt)
{
    extern __shared__ char dyn[];
    const uint32_t sbase = smem_u32(dyn);
    const int bid = blockIdx.x;
    const int tid = threadIdx.x;
    const int wid = tid >> 5;
    const int lid = tid & 31;

    const bool isR = (bid < 256);
    int mt, nt, Ndim, Kdim;
    const fp16 *Ag, *Bg;
    if (isR) { mt = bid >> 2;  nt = bid & 3;   Ndim = MMDIM; Kdim = NCODE; Ag = vsb; Bg = Baa; }
    else     { int u = bid - 256; mt = u >> 4; nt = u & 15;  Ndim = NCODE; Kdim = MMDIM; Ag = rsb; Bg = Bat; }
    const int m0 = mt * 128, n0 = nt * 128;

    // ---- MODE 0 r-path: rs = -z (copy tile; no GEMM) --------------------------
    if (MODE == 0 && isR) {
        const uint32_t* zs = (const uint32_t*)zh;
        uint32_t* rd = (uint32_t*)rsb;
#pragma unroll
        for (int i = 0; i < 32; i++) {
            int e = tid + i * 256;                    // 8192 uint32 per tile
            int r = e >> 6, c = e & 63;
            size_t u32i = (size_t)(m0 + r) * (MMDIM / 2) + (n0 >> 1) + c;
            rd[u32i] = zs[u32i] ^ 0x80008000u;
        }
        ctasignal(&cnt[mt]);
        return;
    }

    if (!isR) ctawait(&cnt[mt], 4);   // all 4 r-tiles of this m-strip done

    const int m_w = (wid >> 2) * 64;
    const int n_w = (wid & 3) * 32;
    const int aRow = (lid & 7) + ((lid >> 3) & 1) * 8;
    const int aK   = ((lid >> 4) & 1) * 8;
    const int bRow = (lid & 7) + ((lid >> 4) & 1) * 8;
    const int bK   = ((lid >> 3) & 1) * 8;
    const uint32_t aOff = (uint32_t)((m_w + aRow) * ROW_B + aK * 2);
    const uint32_t bOff = (uint32_t)((n_w + bRow) * ROW_B + bK * 2);

    float acc[4][4][4];
#pragma unroll
    for (int i = 0; i < 4; i++)
#pragma unroll
        for (int j = 0; j < 4; j++)
#pragma unroll
            for (int c = 0; c < 4; c++) acc[i][j][c] = 0.0f;

    GEMM_MAINLOOP(Ag, Bg, Kdim)

    if (isR) {
        // ---- RSUB epilogue: rs = acc - z (fp16) --------------------------------
#pragma unroll
        for (int i = 0; i < 4; i++)
#pragma unroll
            for (int j = 0; j < 4; j++)
#pragma unroll
                for (int half = 0; half < 2; half++) {
                    const int row = m0 + m_w + i * 16 + (lid >> 2) + half * 8;
                    const int col = n0 + n_w + j * 8 + (lid & 3) * 2;
                    const size_t idx = (size_t)row * MMDIM + col;
                    float o0 = acc[i][j][half * 2];
                    float o1 = acc[i][j][half * 2 + 1];
                    __half2 zv = *(const __half2*)&zh[idx];
                    store2h(rsb, idx, o0 - __half2float(__low2half(zv)),
                                      o1 - __half2float(__high2half(zv)));
                }
        ctasignal(&cnt[mt]);
    } else {
        // ---- FISTA epilogue ----------------------------------------------------
        float eta = expf(leta[kidx]);  eta = fminf(fmaxf(eta, 1e-8f), 10.0f);
        float tau = expf(ltau[kidx]); tau = fminf(fmaxf(tau, 1e-8f), 10.0f);
        const float thr = eta * tau;
#pragma unroll
        for (int i = 0; i < 4; i++)
#pragma unroll
            for (int j = 0; j < 4; j++)
#pragma unroll
                for (int half = 0; half < 2; half++) {
                    const int row = m0 + m_w + i * 16 + (lid >> 2) + half * 8;
                    const int col = n0 + n_w + j * 8 + (lid & 3) * 2;
                    const size_t idx = (size_t)row * NCODE + col;
                    float o0 = acc[i][j][half * 2];
                    float o1 = acc[i][j][half * 2 + 1];
                    if (MODE == 0) {                       // v = 0
                        float a0n = softf(-eta * o0, thr);
                        float a1n = softf(-eta * o1, thr);
                        *(float2*)&adst[idx] = make_float2(a0n, a1n);
                        store2h(vsb, idx, a0n, a1n);       // v1 = alpha1 (beta1=0)
                    } else if (MODE == 1) {
                        float2 ac = *(const float2*)&acur[idx];
                        float2 ap = *(const float2*)&aprev[idx];
                        float v0 = ac.x + betaV * (ac.x - ap.x);
                        float v1 = ac.y + betaV * (ac.y - ap.y);
                        float a0n = softf(v0 - eta * o0, thr);
                        float a1n = softf(v1 - eta * o1, thr);
                        float vn0 = a0n + betaN * (a0n - ac.x);
                        float vn1 = a1n + betaN * (a1n - ac.y);
                        *(float2*)&adst[idx] = make_float2(a0n, a1n);
                        store2h(vsb, idx, vn0, vn1);
                    } else {                               // MODE 2: last
                        float2 ac = *(const float2*)&acur[idx];
                        float2 ap = *(const float2*)&aprev[idx];
                        float v0 = ac.x + betaV * (ac.x - ap.x);
                        float v1 = ac.y + betaV * (ac.y - ap.y);
                        float a0n = softf(v0 - eta * o0, thr);
                        float a1n = softf(v1 - eta * o1, thr);
                        *(float2*)&oalpha[idx] = make_float2(a0n, a1n);
                        store2h(apo, idx, a0n, a1n);
                    }
                }
    }
}

// ---------------- prep kernels ------------------------------------------------
__global__ void round_kernel(const float4* __restrict__ s, fp16* __restrict__ o, int n4)
{
    int i = blockIdx.x * blockDim.x + threadIdx.x;
    if (i < n4) {
        float4 v = s[i];
        size_t idx = (size_t)i * 4;
        *(__half2*)(o + idx)     = __halves2half2(__float2half_rn(v.x), __float2half_rn(v.y));
        *(__half2*)(o + idx + 2) = __halves2half2(__float2half_rn(v.z), __float2half_rn(v.w));
    }
}

__global__ void tround_kernel(const float* __restrict__ s, fp16* __restrict__ o,
                              int R, int C)
{
    __shared__ float t[32][33];
    const int bx = blockIdx.x * 32;
    const int by = blockIdx.y * 32;
    const int x = threadIdx.x, y = threadIdx.y;
#pragma unroll
    for (int i = 0; i < 4; i++)
        t[y + i * 8][x] = s[(size_t)(by + y + i * 8) * C + bx + x];
    __syncthreads();
#pragma unroll
    for (int i = 0; i < 4; i++)
        o[(size_t)(bx + y + i * 8) * R + by + x] = __float2half_rn(t[x][y + i * 8]);
}

__global__ void zcnt_kernel(int* __restrict__ c, int n)
{
    int i = blockIdx.x * blockDim.x + threadIdx.x;
    if (i < n) c[i] = 0;
}

// ---------------------------------------------------------------------------
extern "C" void kernel_launch(void* const* d_in, const int* in_sizes, int n_in,
                              void* d_out, int out_size)
{
    const float* x    = (const float*)d_in[0];
    const float* bvec = (const float*)d_in[1];
    const float* W1   = (const float*)d_in[2];
    const float* b1   = (const float*)d_in[3];
    const float* W2   = (const float*)d_in[4];
    const float* b2   = (const float*)d_in[5];
    const float* W3   = (const float*)d_in[6];
    const float* b3   = (const float*)d_in[7];
    const float* A    = (const float*)d_in[8];
    const float* leta = (const float*)d_in[9];
    const float* ltau = (const float*)d_in[10];
    const float* Psi  = (const float*)d_in[11];
    const float* Mmat = (const float*)d_in[12];

    float* out     = (float*)d_out;
    float* o_ybg   = out;
    float* o_z     = o_ybg   + (size_t)BATCH * NOUTD;
    float* o_alpha = o_z     + (size_t)BATCH * MMDIM;
    float* o_yhat  = o_alpha + (size_t)BATCH * NCODE;

#define SYM(p, s) void* p##_; cudaGetSymbolAddress(&p##_, s); auto* p = (decltype(&s[0]))p##_
    SYM(aA, g_aA);   SYM(aB, g_aB);   SYM(cnt, g_cnt);
    SYM(xs, g_xs);   SYM(h1, g_h1);   SYM(h2, g_h2);   SYM(yb, g_yb);
    SYM(zh, g_zh);   SYM(vs, g_vs);   SYM(rs, g_rs);   SYM(ap, g_ap);
    SYM(w1, g_w1);   SYM(w2, g_w2);   SYM(w3, g_w3);
    SYM(mw, g_m);    SYM(aa, g_aa);   SYM(at, g_at);   SYM(ps, g_ps);
#undef SYM

    cudaFuncSetAttribute((void*)wgemm<EPI_GELU>, cudaFuncAttributeMaxDynamicSharedMemorySize, SMEM_BYTES);
    cudaFuncSetAttribute((void*)wgemm<EPI_YBG>,  cudaFuncAttributeMaxDynamicSharedMemorySize, SMEM_BYTES);
    cudaFuncSetAttribute((void*)wgemm<EPI_ZSUB>, cudaFuncAttributeMaxDynamicSharedMemorySize, SMEM_BYTES);
    cudaFuncSetAttribute((void*)wgemm<EPI_ADD>,  cudaFuncAttributeMaxDynamicSharedMemorySize, SMEM_BYTES);
    cudaFuncSetAttribute((void*)fstep<0>, cudaFuncAttributeMaxDynamicSharedMemorySize, SMEM_BYTES);
    cudaFuncSetAttribute((void*)fstep<1>, cudaFuncAttributeMaxDynamicSharedMemorySize, SMEM_BYTES);
    cudaFuncSetAttribute((void*)fstep<2>, cudaFuncAttributeMaxDynamicSharedMemorySize, SMEM_BYTES);

    // host-side FISTA momentum: betas[k] forms v_k from alpha_k, alpha_{k-1}
    float betas[KSTEPS + 1];
    {
        float t = 1.0f; betas[0] = 0.0f;
        for (int k = 1; k <= KSTEPS; k++) {
            float tn = 0.5f * (1.0f + sqrtf(1.0f + 4.0f * t * t));
            betas[k] = (t - 1.0f) / tn;
            t = tn;
        }
    }

    // ---- prep -----------------------------------------------------------------
    auto rounds = [&](const float* s, fp16* o, size_t n) {
        int n4 = (int)(n / 4);
        round_kernel<<<(n4 + 255) / 256, 256>>>((const float4*)s, o, n4);
    };
    rounds(x,    xs, (size_t)BATCH * PDIM);
    rounds(A,    aa, (size_t)MMDIM * NCODE);
    rounds(Mmat, mw, (size_t)MMDIM * NOUTD);
    rounds(Psi,  ps, (size_t)NOUTD * NCODE);
    tround_kernel<<<dim3(H1DIM / 32, PDIM / 32),  dim3(32, 8)>>>(W1, w1, PDIM,  H1DIM);
    tround_kernel<<<dim3(H2DIM / 32, H1DIM / 32), dim3(32, 8)>>>(W2, w2, H1DIM, H2DIM);
    tround_kernel<<<dim3(NOUTD / 32, H2DIM / 32), dim3(32, 8)>>>(W3, w3, H2DIM, NOUTD);
    tround_kernel<<<dim3(NCODE / 32, MMDIM / 32), dim3(32, 8)>>>(A,  at, MMDIM, NCODE);
    zcnt_kernel<<<(KSTEPS * 64 + 255) / 256, 256>>>(cnt, KSTEPS * 64);

    const dim3 blk(256);
#define GRID(N) dim3((N) / 128, BATCH / 128)
#define NUL0 (float*)nullptr
#define NULH (fp16*)nullptr

    // ---- background MLP + z ---------------------------------------------------
    wgemm<EPI_GELU><<<GRID(H1DIM), blk, SMEM_BYTES>>>(xs, w1, H1DIM, PDIM, NUL0, h1, b1);
    wgemm<EPI_GELU><<<GRID(H2DIM), blk, SMEM_BYTES>>>(h1, w2, H2DIM, H1DIM, NUL0, h2, b2);
    wgemm<EPI_YBG> <<<GRID(NOUTD), blk, SMEM_BYTES>>>(h2, w3, NOUTD, H2DIM, o_ybg, yb, b3);
    wgemm<EPI_ZSUB><<<GRID(MMDIM), blk, SMEM_BYTES>>>(yb, mw, MMDIM, NOUTD, o_z, zh, bvec);

    // ---- FISTA loop: one fused launch per step --------------------------------
    const int FG = 1280;   // 256 r-tiles + 1024 alpha-tiles
    // k = 0: r = -z (copy), alpha_1 = soft(-eta0 * (r0@A))
    fstep<0><<<FG, blk, SMEM_BYTES>>>(aa, at, zh, rs, vs,
        NUL0, NUL0, aA, NUL0, NULH, leta, ltau, 0, 0.f, 0.f, cnt);

    float* cur  = aA;
    float* prev = aB;
    for (int k = 1; k < KSTEPS - 1; k++) {
        const float* pv = (k == 1) ? cur : prev;    // betas[1]=0 -> prev unused
        float* dst = (k == 1) ? aB : prev;
        fstep<1><<<FG, blk, SMEM_BYTES>>>(aa, at, zh, rs, vs,
            cur, pv, dst, NUL0, NULH, leta, ltau, k, betas[k], betas[k + 1],
            cnt + k * 64);
        prev = cur; cur = dst;
    }
    // k = KSTEPS-1 (last)
    fstep<2><<<FG, blk, SMEM_BYTES>>>(aa, at, zh, rs, vs,
        cur, prev, NUL0, o_alpha, ap, leta, ltau, KSTEPS - 1,
        betas[KSTEPS - 1], 0.f, cnt + (KSTEPS - 1) * 64);

    // ---- y_hat = y_bg + alpha @ Psi^T ------------------------------------------
    wgemm<EPI_ADD><<<GRID(NOUTD), blk, SMEM_BYTES>>>(ap, ps, NOUTD, NCODE, o_yhat, NULH, o_ybg);
}

// round 13
// speedup vs baseline: 1.5640x; 1.0091x over previous
#include <cuda_runtime.h>
#include <cuda_fp16.h>
#include <math.h>
#include <stdint.h>

typedef __half fp16;

#define BATCH 8192
#define PDIM  512
#define H1DIM 1024
#define H2DIM 512
#define NOUTD 1024
#define MMDIM 512
#define NCODE 2048
#define KSTEPS 16

// ---------------- device scratch (no allocations allowed) -------------------
__device__ float g_aA[(size_t)BATCH * NCODE];   // alpha odd  (fp32 state)
__device__ float g_aB[(size_t)BATCH * NCODE];   // alpha even (fp32 state)
__device__ int   g_cnt[2 * KSTEPS * 64];        // [0..1023]=cntR, [1024..]=cntA

__device__ fp16 g_xs[(size_t)BATCH*PDIM];
__device__ fp16 g_h1[(size_t)BATCH*H1DIM];
__device__ fp16 g_h2[(size_t)BATCH*H2DIM];
__device__ fp16 g_yb[(size_t)BATCH*NOUTD];
__device__ fp16 g_zh[(size_t)BATCH*MMDIM];   // z fp16
__device__ fp16 g_vs[(size_t)BATCH*NCODE];   // v fp16 (GEMM input)
__device__ fp16 g_rs[(size_t)BATCH*MMDIM];   // r
__device__ fp16 g_ap[(size_t)BATCH*NCODE];   // final alpha fp16

__device__ fp16 g_w1[(size_t)H1DIM*PDIM];    // W1^T
__device__ fp16 g_w2[(size_t)H2DIM*H1DIM];   // W2^T
__device__ fp16 g_w3[(size_t)NOUTD*H2DIM];   // W3^T
__device__ fp16 g_m [(size_t)MMDIM*NOUTD];   // M
__device__ fp16 g_aa[(size_t)MMDIM*NCODE];   // A
__device__ fp16 g_at[(size_t)NCODE*MMDIM];   // A^T
__device__ fp16 g_ps[(size_t)NOUTD*NCODE];   // Psi

// ---------------- PTX helpers -------------------------------------------------
__device__ __forceinline__ uint32_t smem_u32(const void* p) {
    uint32_t a;
    asm("{ .reg .u64 t; cvta.to.shared.u64 t, %1; cvt.u32.u64 %0, t; }" : "=r"(a) : "l"(p));
    return a;
}
__device__ __forceinline__ void cp16(uint32_t d, const void* s) {
    asm volatile("cp.async.cg.shared.global [%0], [%1], 16;" :: "r"(d), "l"(s) : "memory");
}
#define CP_COMMIT() asm volatile("cp.async.commit_group;" ::: "memory")
#define CP_WAIT0()  asm volatile("cp.async.wait_group 0;" ::: "memory")

#define LDSM4(r0, r1, r2, r3, a) \
    asm volatile("ldmatrix.sync.aligned.m8n8.x4.shared.b16 {%0,%1,%2,%3}, [%4];" \
                 : "=r"(r0), "=r"(r1), "=r"(r2), "=r"(r3) : "r"(a))

#define MMA16816(c, a, b) \
    asm volatile("mma.sync.aligned.m16n8k16.row.col.f32.f16.f16.f32 " \
                 "{%0,%1,%2,%3}, {%4,%5,%6,%7}, {%8,%9}, {%0,%1,%2,%3};" \
                 : "+f"((c)[0]), "+f"((c)[1]), "+f"((c)[2]), "+f"((c)[3]) \
                 : "r"((a)[0]), "r"((a)[1]), "r"((a)[2]), "r"((a)[3]), \
                   "r"((b)[0]), "r"((b)[1]))

// CTA dependency wait/signal. Safe under monotone bid dispatch: every wait
// targets strictly-lower bids (validated R12 across 5 waves).
__device__ __forceinline__ void ctawait(const int* p, int tgt) {
    if (threadIdx.x == 0) {
        const volatile int* vp = (const volatile int*)p;
        while (*vp < tgt) __nanosleep(64);
        __threadfence();
    }
    __syncthreads();
}
__device__ __forceinline__ void ctasignal(int* p) {
    __syncthreads();
    if (threadIdx.x == 0) {
        __threadfence();
        atomicAdd(p, 1);
    }
}

// ---------------- GEMM constants ---------------------------------------------
#define ROW_B   144
#define TILE_B  (128 * ROW_B)            // 18432 B
#define STAGE_B (2 * TILE_B)             // 36864 B
#define SMEM_BYTES (2 * STAGE_B)         // 73728 B -> 2 CTAs/SM

enum { EPI_GELU = 0, EPI_YBG, EPI_ZSUB };

__device__ __forceinline__ float gelu_exact(float x) {
    return 0.5f * x * (1.0f + erff(x * 0.70710678118654752440f));
}
__device__ __forceinline__ void store2h(fp16* H, size_t idx, float o0, float o1) {
    *(__half2*)(H + idx) = __halves2half2(__float2half_rn(o0), __float2half_rn(o1));
}
__device__ __forceinline__ float softf(float u, float thr) {
    return copysignf(fmaxf(fabsf(u) - thr, 0.0f), u);
}
// betas[j]: identical fp32 recurrence as the reference (betas[0]=betas[1]=0)
__device__ __forceinline__ float beta_of(int j) {
    float t = 1.0f, b = 0.0f;
    for (int i = 1; i <= j; i++) {
        float tn = 0.5f * (1.0f + sqrtf(1.0f + 4.0f * t * t));
        b = (t - 1.0f) / tn;
        t = tn;
    }
    return b;
}

// ---- shared GEMM mainloop (A[M,K] * B[N,K]^T, fp16, fp32 acc) ----------------
#define GEMM_MAINLOOP(Ag, Bg, Kdim)                                            \
    const fp16* gp[8];                                                          \
    uint32_t so[8];                                                             \
    {                                                                           \
        const fp16* srcs[2] = { (Ag), (Bg) };                                   \
        _Pragma("unroll")                                                       \
        for (int it = 0; it < 8; it++) {                                        \
            const int op  = it >> 2;                                            \
            const int row = (it & 3) * 32 + (tid >> 3);                         \
            const int seg = tid & 7;                                            \
            const int rb  = (op == 0) ? m0 : n0;                                \
            gp[it] = srcs[op] + (size_t)(rb + row) * (Kdim) + seg * 8;          \
            so[it] = (uint32_t)(op * TILE_B + row * ROW_B + seg * 16);          \
        }                                                                       \
    }                                                                           \
    _Pragma("unroll")                                                           \
    for (int it = 0; it < 8; it++) cp16(sbase + so[it], gp[it]);                \
    CP_COMMIT();                                                                \
    const int S = (Kdim) >> 6;                                                  \
    for (int s = 0; s < S; s++) {                                               \
        CP_WAIT0();                                                             \
        __syncthreads();                                                        \
        if (s + 1 < S) {                                                        \
            const uint32_t db = sbase + (uint32_t)(((s + 1) & 1) * STAGE_B);    \
            const int k0 = (s + 1) * 64;                                        \
            _Pragma("unroll")                                                   \
            for (int it = 0; it < 8; it++) cp16(db + so[it], gp[it] + k0);      \
            CP_COMMIT();                                                        \
        }                                                                       \
        const uint32_t st = sbase + (uint32_t)((s & 1) * STAGE_B);              \
        _Pragma("unroll")                                                       \
        for (int kk = 0; kk < 4; kk++) {                                        \
            uint32_t ah[4][4], bh[4][2];                                        \
            _Pragma("unroll")                                                   \
            for (int i = 0; i < 4; i++)                                         \
                LDSM4(ah[i][0], ah[i][1], ah[i][2], ah[i][3],                   \
                      st + aOff + i * (16 * ROW_B) + kk * 32);                  \
            _Pragma("unroll")                                                   \
            for (int j = 0; j < 2; j++) {                                       \
                uint32_t r0, r1, r2, r3;                                        \
                LDSM4(r0, r1, r2, r3,                                           \
                      st + TILE_B + bOff + j * (16 * ROW_B) + kk * 32);         \
                bh[2 * j][0] = r0; bh[2 * j][1] = r1;                           \
                bh[2 * j + 1][0] = r2; bh[2 * j + 1][1] = r3;                   \
            }                                                                   \
            _Pragma("unroll")                                                   \
            for (int i = 0; i < 4; i++)                                         \
                _Pragma("unroll")                                               \
                for (int j = 0; j < 4; j++)                                     \
                    MMA16816(acc[i][j], ah[i], bh[j]);                          \
        }                                                                       \
    }

#define EPI_LOOP_BEGIN(NDIM)                                                   \
    _Pragma("unroll")                                                           \
    for (int i = 0; i < 4; i++)                                                 \
        _Pragma("unroll")                                                       \
        for (int j = 0; j < 4; j++)                                             \
            _Pragma("unroll")                                                   \
            for (int half = 0; half < 2; half++) {                              \
                const int row = m0 + m_w + i * 16 + (lid >> 2) + half * 8;      \
                const int col = n0 + n_w + j * 8 + (lid & 3) * 2;               \
                const size_t idx = (size_t)row * (NDIM) + col;                  \
                float o0 = acc[i][j][half * 2];                                 \
                float o1 = acc[i][j][half * 2 + 1];
#define EPI_LOOP_END }

// ---------------------------------------------------------------------------
// wgemm: standalone GEMM for MLP / z phases.
// ---------------------------------------------------------------------------
template <int EPI>
__global__ void __launch_bounds__(256, 2)
wgemm(const fp16* __restrict__ Ag, const fp16* __restrict__ Bg,
      int Ndim, int Kdim,
      float* __restrict__ C0, fp16* __restrict__ Ch,
      const float* __restrict__ aux)
{
    extern __shared__ char dyn[];
    const uint32_t sbase = smem_u32(dyn);
    const int tid = threadIdx.x;
    const int wid = tid >> 5;
    const int lid = tid & 31;
    const int m0  = blockIdx.y * 128;
    const int n0  = blockIdx.x * 128;
    const int m_w = (wid >> 2) * 64;
    const int n_w = (wid & 3) * 32;

    const int aRow = (lid & 7) + ((lid >> 3) & 1) * 8;
    const int aK   = ((lid >> 4) & 1) * 8;
    const int bRow = (lid & 7) + ((lid >> 4) & 1) * 8;
    const int bK   = ((lid >> 3) & 1) * 8;
    const uint32_t aOff = (uint32_t)((m_w + aRow) * ROW_B + aK * 2);
    const uint32_t bOff = (uint32_t)((n_w + bRow) * ROW_B + bK * 2);

    float acc[4][4][4];
#pragma unroll
    for (int i = 0; i < 4; i++)
#pragma unroll
        for (int j = 0; j < 4; j++)
#pragma unroll
            for (int c = 0; c < 4; c++) acc[i][j][c] = 0.0f;

    GEMM_MAINLOOP(Ag, Bg, Kdim)

    EPI_LOOP_BEGIN(Ndim)
        if (EPI == EPI_GELU) {
            float2 bv = *(const float2*)&aux[col];
            store2h(Ch, idx, gelu_exact(o0 + bv.x), gelu_exact(o1 + bv.y));
        } else if (EPI == EPI_YBG) {
            float2 bv = *(const float2*)&aux[col];
            o0 += bv.x; o1 += bv.y;
            *(float2*)&C0[idx] = make_float2(o0, o1);
            store2h(Ch, idx, o0, o1);
        } else {                                   // EPI_ZSUB
            float2 av = *(const float2*)&aux[idx];
            float z0 = av.x - o0, z1 = av.y - o1;
            *(float2*)&C0[idx] = make_float2(z0, z1);
            store2h(Ch, idx, z0, z1);
        }
    EPI_LOOP_END
}

// ---------------------------------------------------------------------------
// floop: ALL 16 FISTA steps + yhat in ONE launch.
//   bid in [k*1280, k*1280+256)      : r-tile of step k
//   bid in [k*1280+256, (k+1)*1280)  : alpha-tile of step k
//   bid >= KSTEPS*1280               : yhat tile (512)
// ---------------------------------------------------------------------------
__global__ void __launch_bounds__(256, 2)
floop(const fp16* __restrict__ Baa, const fp16* __restrict__ Bat,
      const fp16* __restrict__ Bps,
      const fp16* __restrict__ zh, fp16* __restrict__ rsb,
      fp16* __restrict__ vsb, fp16* __restrict__ apo,
      float* __restrict__ aAb, float* __restrict__ aBb,
      float* __restrict__ oalpha, float* __restrict__ oyhat,
      const float* __restrict__ oybg,
      const float* __restrict__ leta, const float* __restrict__ ltau,
      int* __restrict__ cnt)
{
    extern __shared__ char dyn[];
    const uint32_t sbase = smem_u32(dyn);
    const int bid = blockIdx.x;
    const int tid = threadIdx.x;
    const int wid = tid >> 5;
    const int lid = tid & 31;

    int* cntR = cnt;
    int* cntA = cnt + KSTEPS * 64;

    // ---- decode -----------------------------------------------------------------
    int typ;             // 0 = r, 1 = alpha, 2 = yhat
    int k = 0, mt, nt, Ndim, Kdim;
    const fp16 *Ag, *Bg;
    if (bid < KSTEPS * 1280) {
        k = bid / 1280;
        int u = bid - k * 1280;
        if (u < 256) { typ = 0; mt = u >> 2; nt = u & 3;
                       Ndim = MMDIM; Kdim = NCODE; Ag = vsb; Bg = Baa; }
        else { int u2 = u - 256; typ = 1; mt = u2 >> 4; nt = u2 & 15;
               Ndim = NCODE; Kdim = MMDIM; Ag = rsb; Bg = Bat; }
    } else {
        int u = bid - KSTEPS * 1280;
        typ = 2; mt = u >> 3; nt = u & 7;
        Ndim = NOUTD; Kdim = NCODE; Ag = apo; Bg = Bps;
    }
    const int m0 = mt * 128, n0 = nt * 128;

    // ---- step-0 r path: rs = -z (copy) -------------------------------------------
    if (typ == 0 && k == 0) {
        const uint32_t* zs = (const uint32_t*)zh;
        uint32_t* rd = (uint32_t*)rsb;
#pragma unroll
        for (int i = 0; i < 32; i++) {
            int e = tid + i * 256;
            int r = e >> 6, c = e & 63;
            size_t u32i = (size_t)(m0 + r) * (MMDIM / 2) + (n0 >> 1) + c;
            rd[u32i] = zs[u32i] ^ 0x80008000u;
        }
        ctasignal(&cntR[mt]);
        return;
    }

    // ---- dependency waits ----------------------------------------------------------
    if (typ == 0)       ctawait(&cntA[(k - 1) * 64 + mt], 16);  // v_k strip done
    else if (typ == 1)  ctawait(&cntR[k * 64 + mt], 4);         // r strip done
    else                ctawait(&cntA[(KSTEPS - 1) * 64 + mt], 16);

    const int m_w = (wid >> 2) * 64;
    const int n_w = (wid & 3) * 32;
    const int aRow = (lid & 7) + ((lid >> 3) & 1) * 8;
    const int aK   = ((lid >> 4) & 1) * 8;
    const int bRow = (lid & 7) + ((lid >> 4) & 1) * 8;
    const int bK   = ((lid >> 3) & 1) * 8;
    const uint32_t aOff = (uint32_t)((m_w + aRow) * ROW_B + aK * 2);
    const uint32_t bOff = (uint32_t)((n_w + bRow) * ROW_B + bK * 2);

    float acc[4][4][4];
#pragma unroll
    for (int i = 0; i < 4; i++)
#pragma unroll
        for (int j = 0; j < 4; j++)
#pragma unroll
            for (int c = 0; c < 4; c++) acc[i][j][c] = 0.0f;

    GEMM_MAINLOOP(Ag, Bg, Kdim)

    if (typ == 0) {
        // ---- r epilogue: rs = acc - z ------------------------------------------------
        EPI_LOOP_BEGIN(MMDIM)
            __half2 zv = *(const __half2*)&zh[idx];
            store2h(rsb, idx, o0 - __half2float(__low2half(zv)),
                              o1 - __half2float(__high2half(zv)));
        EPI_LOOP_END
        ctasignal(&cntR[k * 64 + mt]);
    } else if (typ == 1) {
        // ---- alpha epilogue -----------------------------------------------------------
        float eta = expf(leta[k]);  eta = fminf(fmaxf(eta, 1e-8f), 10.0f);
        float tau = expf(ltau[k]); tau = fminf(fmaxf(tau, 1e-8f), 10.0f);
        const float thr = eta * tau;
        if (k == 0) {
            float* adst = aAb;                      // alpha_1 -> aA
            EPI_LOOP_BEGIN(NCODE)
                float a0n = softf(-eta * o0, thr);
                float a1n = softf(-eta * o1, thr);
                *(float2*)&adst[idx] = make_float2(a0n, a1n);
                store2h(vsb, idx, a0n, a1n);        // v1 = alpha_1 (beta1 = 0)
            EPI_LOOP_END
        } else if (k < KSTEPS - 1) {
            const float betaV = beta_of(k);
            const float betaN = beta_of(k + 1);
            const float* acur  = (k & 1) ? aAb : aBb;     // alpha_k
            const float* aprev = (k == 1) ? acur : ((k & 1) ? aBb : aAb);
            float* adst = (k & 1) ? aBb : aAb;            // alpha_{k+1}
            EPI_LOOP_BEGIN(NCODE)
                float2 ac = *(const float2*)&acur[idx];
                float2 ap = *(const float2*)&aprev[idx];
                float v0 = ac.x + betaV * (ac.x - ap.x);
                float v1 = ac.y + betaV * (ac.y - ap.y);
                float a0n = softf(v0 - eta * o0, thr);
                float a1n = softf(v1 - eta * o1, thr);
                float vn0 = a0n + betaN * (a0n - ac.x);
                float vn1 = a1n + betaN * (a1n - ac.y);
                *(float2*)&adst[idx] = make_float2(a0n, a1n);
                store2h(vsb, idx, vn0, vn1);
            EPI_LOOP_END
        } else {
            const float betaV = beta_of(KSTEPS - 1);
            const float* acur  = aAb;               // alpha_15 (odd)
            const float* aprev = aBb;               // alpha_14
            EPI_LOOP_BEGIN(NCODE)
                float2 ac = *(const float2*)&acur[idx];
                float2 ap = *(const float2*)&aprev[idx];
                float v0 = ac.x + betaV * (ac.x - ap.x);
                float v1 = ac.y + betaV * (ac.y - ap.y);
                float a0n = softf(v0 - eta * o0, thr);
                float a1n = softf(v1 - eta * o1, thr);
                *(float2*)&oalpha[idx] = make_float2(a0n, a1n);
                store2h(apo, idx, a0n, a1n);
            EPI_LOOP_END
        }
        ctasignal(&cntA[k * 64 + mt]);
    } else {
        // ---- yhat epilogue: yhat = acc + ybg ------------------------------------------
        EPI_LOOP_BEGIN(NOUTD)
            float2 yv = *(const float2*)&oybg[idx];
            *(float2*)&oyhat[idx] = make_float2(o0 + yv.x, o1 + yv.y);
        EPI_LOOP_END
    }
}

// ---------------- prep kernels ------------------------------------------------
__global__ void round_kernel(const float4* __restrict__ s, fp16* __restrict__ o, int n4)
{
    int i = blockIdx.x * blockDim.x + threadIdx.x;
    if (i < n4) {
        float4 v = s[i];
        size_t idx = (size_t)i * 4;
        *(__half2*)(o + idx)     = __halves2half2(__float2half_rn(v.x), __float2half_rn(v.y));
        *(__half2*)(o + idx + 2) = __halves2half2(__float2half_rn(v.z), __float2half_rn(v.w));
    }
}

__global__ void tround_kernel(const float* __restrict__ s, fp16* __restrict__ o,
                              int R, int C)
{
    __shared__ float t[32][33];
    const int bx = blockIdx.x * 32;
    const int by = blockIdx.y * 32;
    const int x = threadIdx.x, y = threadIdx.y;
#pragma unroll
    for (int i = 0; i < 4; i++)
        t[y + i * 8][x] = s[(size_t)(by + y + i * 8) * C + bx + x];
    __syncthreads();
#pragma unroll
    for (int i = 0; i < 4; i++)
        o[(size_t)(bx + y + i * 8) * R + by + x] = __float2half_rn(t[x][y + i * 8]);
}

__global__ void zcnt_kernel(int* __restrict__ c, int n)
{
    int i = blockIdx.x * blockDim.x + threadIdx.x;
    if (i < n) c[i] = 0;
}

// ---------------------------------------------------------------------------
extern "C" void kernel_launch(void* const* d_in, const int* in_sizes, int n_in,
                              void* d_out, int out_size)
{
    const float* x    = (const float*)d_in[0];
    const float* bvec = (const float*)d_in[1];
    const float* W1   = (const float*)d_in[2];
    const float* b1   = (const float*)d_in[3];
    const float* W2   = (const float*)d_in[4];
    const float* b2   = (const float*)d_in[5];
    const float* W3   = (const float*)d_in[6];
    const float* b3   = (const float*)d_in[7];
    const float* A    = (const float*)d_in[8];
    const float* leta = (const float*)d_in[9];
    const float* ltau = (const float*)d_in[10];
    const float* Psi  = (const float*)d_in[11];
    const float* Mmat = (const float*)d_in[12];

    float* out     = (float*)d_out;
    float* o_ybg   = out;
    float* o_z     = o_ybg   + (size_t)BATCH * NOUTD;
    float* o_alpha = o_z     + (size_t)BATCH * MMDIM;
    float* o_yhat  = o_alpha + (size_t)BATCH * NCODE;

#define SYM(p, s) void* p##_; cudaGetSymbolAddress(&p##_, s); auto* p = (decltype(&s[0]))p##_
    SYM(aA, g_aA);   SYM(aB, g_aB);   SYM(cnt, g_cnt);
    SYM(xs, g_xs);   SYM(h1, g_h1);   SYM(h2, g_h2);   SYM(yb, g_yb);
    SYM(zh, g_zh);   SYM(vs, g_vs);   SYM(rs, g_rs);   SYM(ap, g_ap);
    SYM(w1, g_w1);   SYM(w2, g_w2);   SYM(w3, g_w3);
    SYM(mw, g_m);    SYM(aa, g_aa);   SYM(at, g_at);   SYM(ps, g_ps);
#undef SYM

    cudaFuncSetAttribute((void*)wgemm<EPI_GELU>, cudaFuncAttributeMaxDynamicSharedMemorySize, SMEM_BYTES);
    cudaFuncSetAttribute((void*)wgemm<EPI_YBG>,  cudaFuncAttributeMaxDynamicSharedMemorySize, SMEM_BYTES);
    cudaFuncSetAttribute((void*)wgemm<EPI_ZSUB>, cudaFuncAttributeMaxDynamicSharedMemorySize, SMEM_BYTES);
    cudaFuncSetAttribute((void*)floop, cudaFuncAttributeMaxDynamicSharedMemorySize, SMEM_BYTES);

    // ---- prep -----------------------------------------------------------------
    auto rounds = [&](const float* s, fp16* o, size_t n) {
        int n4 = (int)(n / 4);
        round_kernel<<<(n4 + 255) / 256, 256>>>((const float4*)s, o, n4);
    };
    rounds(x,    xs, (size_t)BATCH * PDIM);
    rounds(A,    aa, (size_t)MMDIM * NCODE);
    rounds(Mmat, mw, (size_t)MMDIM * NOUTD);
    rounds(Psi,  ps, (size_t)NOUTD * NCODE);
    tround_kernel<<<dim3(H1DIM / 32, PDIM / 32),  dim3(32, 8)>>>(W1, w1, PDIM,  H1DIM);
    tround_kernel<<<dim3(H2DIM / 32, H1DIM / 32), dim3(32, 8)>>>(W2, w2, H1DIM, H2DIM);
    tround_kernel<<<dim3(NOUTD / 32, H2DIM / 32), dim3(32, 8)>>>(W3, w3, H2DIM, NOUTD);
    tround_kernel<<<dim3(NCODE / 32, MMDIM / 32), dim3(32, 8)>>>(A,  at, MMDIM, NCODE);
    zcnt_kernel<<<(2 * KSTEPS * 64 + 255) / 256, 256>>>(cnt, 2 * KSTEPS * 64);

    const dim3 blk(256);
#define GRID(N) dim3((N) / 128, BATCH / 128)
#define NUL0 (float*)nullptr
#define NULH (fp16*)nullptr

    // ---- background MLP + z ---------------------------------------------------
    wgemm<EPI_GELU><<<GRID(H1DIM), blk, SMEM_BYTES>>>(xs, w1, H1DIM, PDIM, NUL0, h1, b1);
    wgemm<EPI_GELU><<<GRID(H2DIM), blk, SMEM_BYTES>>>(h1, w2, H2DIM, H1DIM, NUL0, h2, b2);
    wgemm<EPI_YBG> <<<GRID(NOUTD), blk, SMEM_BYTES>>>(h2, w3, NOUTD, H2DIM, o_ybg, yb, b3);
    wgemm<EPI_ZSUB><<<GRID(MMDIM), blk, SMEM_BYTES>>>(yb, mw, MMDIM, NOUTD, o_z, zh, bvec);

    // ---- all 16 FISTA steps + yhat in ONE launch --------------------------------
    const int FG = KSTEPS * 1280 + 512;   // 20992
    floop<<<FG, blk, SMEM_BYTES>>>(aa, at, ps, zh, rs, vs, ap,
                                   aA, aB, o_alpha, o_yhat, o_ybg,
                                   leta, ltau, cnt);
}